// round 1
// baseline (speedup 1.0000x reference)
#include <cuda_runtime.h>
#include <cuda_bf16.h>
#include <math.h>

typedef unsigned long long ull;

// Problem constants
#define Bc 64
#define Tc 512
#define Ic 2048
#define Hc 256
#define Gc 768   // 3*H

// ---------------- device scratch (no allocations allowed) ----------------
__device__ float g_xg[(size_t)Bc * Tc * Gc];   // 96 MB, reused per layer
__device__ float g_y0[(size_t)Bc * Tc * Hc];   // layer0 output
__device__ float g_y1[(size_t)Bc * Tc * Hc];   // layer1 output
__device__ float g_y2[(size_t)Bc * Tc * Hc];   // layer2 output
__device__ float g_h[2][Bc * Hc];              // double-buffered hidden state
__device__ ull   g_bar;                        // grid barrier counter

// ---------------- packed f32x2 helpers ----------------
__device__ __forceinline__ ull pack2(float x, float y) {
    ull r; asm("mov.b64 %0, {%1, %2};" : "=l"(r) : "f"(x), "f"(y)); return r;
}
__device__ __forceinline__ void unpack2(ull v, float& x, float& y) {
    asm("mov.b64 {%0, %1}, %2;" : "=f"(x), "=f"(y) : "l"(v));
}
__device__ __forceinline__ ull fma2(ull a, ull b, ull c) {
    ull d; asm("fma.rn.f32x2 %0, %1, %2, %3;" : "=l"(d) : "l"(a), "l"(b), "l"(c)); return d;
}

__device__ __forceinline__ float sigmoidf_(float x) {
    return 1.0f / (1.0f + __expf(-x));
}

// ---------------- GEMM: C[m,g] = sum_k A[m,k] * W[g,k] + bias[g] ----------------
// M = Bc*Tc = 32768 (rows), N = 768, K in {2048, 256}. BM=BN=128, BK=16, 256 thr, 8x8/thread.
__global__ __launch_bounds__(256) void gemm_xg(const float* __restrict__ Aext, int src, int K,
                                               const float* __restrict__ W,
                                               const float* __restrict__ bias) {
    const float* A = (src == 0) ? Aext : (src == 1 ? g_y0 : g_y1);
    float* C = g_xg;
    __shared__ float As[16][128];
    __shared__ float Ws[16][128];
    int tid = threadIdx.x;
    int m0 = blockIdx.y * 128;
    int n0 = blockIdx.x * 128;
    int lr = tid >> 2;            // 0..63
    int lc = (tid & 3) << 2;      // 0,4,8,12
    int tx = tid & 15, ty = tid >> 4;

    ull acc[8][4];
#pragma unroll
    for (int i = 0; i < 8; i++)
#pragma unroll
        for (int j = 0; j < 4; j++) acc[i][j] = 0ULL;

    const float* Ap = A + (size_t)(m0 + lr) * K + lc;
    const float* Wp = W + (size_t)(n0 + lr) * K + lc;

    for (int k0 = 0; k0 < K; k0 += 16) {
        float4 a0 = *(const float4*)(Ap + k0);
        float4 a1 = *(const float4*)(Ap + (size_t)64 * K + k0);
        float4 w0 = *(const float4*)(Wp + k0);
        float4 w1 = *(const float4*)(Wp + (size_t)64 * K + k0);
        __syncthreads();
        As[lc + 0][lr] = a0.x; As[lc + 1][lr] = a0.y; As[lc + 2][lr] = a0.z; As[lc + 3][lr] = a0.w;
        As[lc + 0][lr + 64] = a1.x; As[lc + 1][lr + 64] = a1.y; As[lc + 2][lr + 64] = a1.z; As[lc + 3][lr + 64] = a1.w;
        Ws[lc + 0][lr] = w0.x; Ws[lc + 1][lr] = w0.y; Ws[lc + 2][lr] = w0.z; Ws[lc + 3][lr] = w0.w;
        Ws[lc + 0][lr + 64] = w1.x; Ws[lc + 1][lr + 64] = w1.y; Ws[lc + 2][lr + 64] = w1.z; Ws[lc + 3][lr + 64] = w1.w;
        __syncthreads();
#pragma unroll
        for (int kk = 0; kk < 16; kk++) {
            float4 av0 = *(const float4*)&As[kk][ty * 8];
            float4 av1 = *(const float4*)&As[kk][ty * 8 + 4];
            ulonglong2 b0 = *(const ulonglong2*)&Ws[kk][tx * 8];
            ulonglong2 b1 = *(const ulonglong2*)&Ws[kk][tx * 8 + 4];
            float a[8] = {av0.x, av0.y, av0.z, av0.w, av1.x, av1.y, av1.z, av1.w};
            ull bb[4] = {b0.x, b0.y, b1.x, b1.y};
#pragma unroll
            for (int i = 0; i < 8; i++) {
                ull ad = pack2(a[i], a[i]);
#pragma unroll
                for (int j = 0; j < 4; j++) acc[i][j] = fma2(ad, bb[j], acc[i][j]);
            }
        }
    }

    float bsv[8];
#pragma unroll
    for (int j = 0; j < 8; j++) bsv[j] = bias[n0 + tx * 8 + j];
#pragma unroll
    for (int i = 0; i < 8; i++) {
        float o[8];
        unpack2(acc[i][0], o[0], o[1]);
        unpack2(acc[i][1], o[2], o[3]);
        unpack2(acc[i][2], o[4], o[5]);
        unpack2(acc[i][3], o[6], o[7]);
        size_t row = (size_t)(m0 + ty * 8 + i) * Gc + n0 + tx * 8;
        float4 s0 = make_float4(o[0] + bsv[0], o[1] + bsv[1], o[2] + bsv[2], o[3] + bsv[3]);
        float4 s1 = make_float4(o[4] + bsv[4], o[5] + bsv[5], o[6] + bsv[6], o[7] + bsv[7]);
        *(float4*)&C[row] = s0;
        *(float4*)&C[row + 4] = s1;
    }
}

// ---------------- barrier reset ----------------
__global__ void reset_bar() { g_bar = 0ULL; }

// ---------------- persistent recurrent scan ----------------
// grid: (8 hidden-groups, 8 batch-groups) = 64 blocks, 192 threads each.
// Each block: 8 batch rows x 32 hidden units (96 gate rows). w_hh slice persistent in SMEM.
#define SCAN_THREADS 192
#define W_SH_FLOATS (256 * 96)
#define H_STRIDE 260
#define SCAN_SMEM_FLOATS (W_SH_FLOATS + 8 * H_STRIDE + 8 * 96 + 96)
#define SCAN_SMEM_BYTES (SCAN_SMEM_FLOATS * 4)

__device__ __forceinline__ void grid_barrier(ull target) {
    if (threadIdx.x == 0) {
        __threadfence();
        atomicAdd(&g_bar, 1ULL);
        while (*((volatile ull*)&g_bar) < target) { }
        __threadfence();
    }
    __syncthreads();
}

__global__ __launch_bounds__(SCAN_THREADS) void scan_kernel(const float* __restrict__ w_hh,
                                                            const float* __restrict__ b_hh,
                                                            int layer) {
    extern __shared__ float smem[];
    float* w_sh  = smem;                     // [256][96] (k-major)
    float* h_sh  = smem + W_SH_FLOATS;       // [8][260]
    float* hg_sh = h_sh + 8 * H_STRIDE;      // [8][96]
    float* b_sh  = hg_sh + 8 * 96;           // [96]

    const float* xg = g_xg;
    float* yout = (layer == 0) ? g_y0 : (layer == 1 ? g_y1 : g_y2);

    int tid = threadIdx.x;
    int gh = blockIdx.x;   // hidden group 0..7
    int gb = blockIdx.y;   // batch group 0..7
    int j0 = gh * 32;
    int b0 = gb * 8;

    // load w_hh slice transposed into shared: local gate col c = s*32+jj -> global row s*256+j0+jj
    for (int idx = tid; idx < 96 * 256; idx += SCAN_THREADS) {
        int c = idx >> 8;
        int k = idx & 255;
        int s = c >> 5;
        int jj = c & 31;
        int grow = s * 256 + j0 + jj;
        w_sh[k * 96 + c] = w_hh[(size_t)grow * 256 + k];
    }
    if (tid < 96) {
        int s = tid >> 5, jj = tid & 31;
        b_sh[tid] = b_hh[s * 256 + j0 + jj];
    }
    // zero our slice of h buffer 0
    for (int idx = tid; idx < 256; idx += SCAN_THREADS) {
        int b = idx >> 5, jj = idx & 31;
        g_h[0][(b0 + b) * 256 + j0 + jj] = 0.0f;
    }
    grid_barrier(64ULL);

    const int bx = tid % 48, by = tid / 48;
    const int g0 = bx * 2;       // gate col pair
    const int bp = by * 2;       // batch pair base

    for (int t = 0; t < Tc; t++) {
        int p = t & 1;
        const float* hread = g_h[p];
        float* hwrite = g_h[p ^ 1];

        // stage h (8 rows x 256) from global into shared (L2-coherent loads)
        for (int v = tid; v < 512; v += SCAN_THREADS) {
            int b = v >> 6, kk = v & 63;
            float4 hv = __ldcg((const float4*)(hread + (size_t)(b0 + b) * 256) + kk);
            *((float4*)(h_sh + b * H_STRIDE) + kk) = hv;
        }
        // prefetch xg values for pointwise phase (hide DRAM latency behind GEMM)
        float xr1, xz1, xn1, xr2 = 0.f, xz2 = 0.f, xn2 = 0.f;
        {
            int idx = tid; int b = idx >> 5, jj = idx & 31;
            const float* xp = xg + ((size_t)(b0 + b) * Tc + t) * Gc + (j0 + jj);
            xr1 = __ldg(xp); xz1 = __ldg(xp + 256); xn1 = __ldg(xp + 512);
        }
        if (tid < 64) {
            int idx = tid + SCAN_THREADS; int b = idx >> 5, jj = idx & 31;
            const float* xp = xg + ((size_t)(b0 + b) * Tc + t) * Gc + (j0 + jj);
            xr2 = __ldg(xp); xz2 = __ldg(xp + 256); xn2 = __ldg(xp + 512);
        }
        __syncthreads();

        // hg = h @ w_slice^T : per-thread 2 batches x 2 gate cols, packed f32x2 FMA
        ull acc0 = 0ULL, acc1 = 0ULL;
        const float4* h0v = (const float4*)(h_sh + bp * H_STRIDE);
        const float4* h1v = (const float4*)(h_sh + (bp + 1) * H_STRIDE);
#pragma unroll 8
        for (int k4 = 0; k4 < 64; k4++) {
            float4 h0 = h0v[k4], h1 = h1v[k4];
            float h0a[4] = {h0.x, h0.y, h0.z, h0.w};
            float h1a[4] = {h1.x, h1.y, h1.z, h1.w};
#pragma unroll
            for (int j = 0; j < 4; j++) {
                ull wv = *(const ull*)(w_sh + (size_t)(k4 * 4 + j) * 96 + g0);
                acc0 = fma2(pack2(h0a[j], h0a[j]), wv, acc0);
                acc1 = fma2(pack2(h1a[j], h1a[j]), wv, acc1);
            }
        }
        {
            float a0x, a0y, a1x, a1y;
            unpack2(acc0, a0x, a0y);
            unpack2(acc1, a1x, a1y);
            float bb0 = b_sh[g0], bb1 = b_sh[g0 + 1];
            *(float2*)&hg_sh[bp * 96 + g0] = make_float2(a0x + bb0, a0y + bb1);
            *(float2*)&hg_sh[(bp + 1) * 96 + g0] = make_float2(a1x + bb0, a1y + bb1);
        }
        __syncthreads();

        // pointwise gates + state update + outputs
        {
            int idx = tid;
            int b = idx >> 5, jj = idx & 31;
            float hr = hg_sh[b * 96 + jj];
            float hz = hg_sh[b * 96 + 32 + jj];
            float hn = hg_sh[b * 96 + 64 + jj];
            float hprev = h_sh[b * H_STRIDE + j0 + jj];
            float r = sigmoidf_(xr1 + hr);
            float z = sigmoidf_(xz1 + hz);
            float n = tanhf(xn1 + r * hn);
            float hnew = fmaf(z, hprev - n, n);
            __stcg(hwrite + (size_t)(b0 + b) * 256 + j0 + jj, hnew);
            yout[((size_t)(b0 + b) * Tc + t) * Hc + j0 + jj] = hnew;
        }
        if (tid < 64) {
            int idx = tid + SCAN_THREADS;
            int b = idx >> 5, jj = idx & 31;
            float hr = hg_sh[b * 96 + jj];
            float hz = hg_sh[b * 96 + 32 + jj];
            float hn = hg_sh[b * 96 + 64 + jj];
            float hprev = h_sh[b * H_STRIDE + j0 + jj];
            float r = sigmoidf_(xr2 + hr);
            float z = sigmoidf_(xz2 + hz);
            float n = tanhf(xn2 + r * hn);
            float hnew = fmaf(z, hprev - n, n);
            __stcg(hwrite + (size_t)(b0 + b) * 256 + j0 + jj, hnew);
            yout[((size_t)(b0 + b) * Tc + t) * Hc + j0 + jj] = hnew;
        }

        if (t < Tc - 1) {
            grid_barrier(64ULL * (ull)(t + 2));
        }
    }
}

// ---------------- FC head ----------------
__global__ __launch_bounds__(128) void fc_kernel(const float* __restrict__ fc1_w,
                                                 const float* __restrict__ fc1_b,
                                                 const float* __restrict__ fco_w,
                                                 const float* __restrict__ fco_b,
                                                 float* __restrict__ out) {
    int b = blockIdx.x;
    int f = threadIdx.x;
    const float* last = g_y2 + ((size_t)b * Tc + (Tc - 1)) * Hc;
    __shared__ float ls[256];
    for (int k = f; k < 256; k += 128) ls[k] = last[k];
    __syncthreads();
    float acc = fc1_b[f];
    const float* wr = fc1_w + (size_t)f * 256;
#pragma unroll 8
    for (int k = 0; k < 256; k++) acc = fmaf(ls[k], wr[k], acc);
    float z = fmaxf(acc, 0.0f);
    float v = z * fco_w[f];
#pragma unroll
    for (int o = 16; o > 0; o >>= 1) v += __shfl_xor_sync(0xffffffffu, v, o);
    __shared__ float ws[4];
    if ((f & 31) == 0) ws[f >> 5] = v;
    __syncthreads();
    if (f == 0) out[b] = ws[0] + ws[1] + ws[2] + ws[3] + fco_b[0];
}

// ---------------- launch ----------------
extern "C" void kernel_launch(void* const* d_in, const int* in_sizes, int n_in,
                              void* d_out, int out_size) {
    const float* x     = (const float*)d_in[0];
    const float* w_ih0 = (const float*)d_in[1];
    const float* w_hh0 = (const float*)d_in[2];
    const float* b_ih0 = (const float*)d_in[3];
    const float* b_hh0 = (const float*)d_in[4];
    const float* w_ih1 = (const float*)d_in[5];
    const float* w_hh1 = (const float*)d_in[6];
    const float* b_ih1 = (const float*)d_in[7];
    const float* b_hh1 = (const float*)d_in[8];
    const float* w_ih2 = (const float*)d_in[9];
    const float* w_hh2 = (const float*)d_in[10];
    const float* b_ih2 = (const float*)d_in[11];
    const float* b_hh2 = (const float*)d_in[12];
    const float* fc1_w = (const float*)d_in[13];
    const float* fc1_b = (const float*)d_in[14];
    const float* fco_w = (const float*)d_in[15];
    const float* fco_b = (const float*)d_in[16];
    float* out = (float*)d_out;

    cudaFuncSetAttribute(scan_kernel, cudaFuncAttributeMaxDynamicSharedMemorySize, SCAN_SMEM_BYTES);

    dim3 ggrid(6, 256);      // N tiles x M tiles
    dim3 sgrid(8, 8);        // hidden groups x batch groups

    // layer 0
    gemm_xg<<<ggrid, 256>>>(x, 0, Ic, w_ih0, b_ih0);
    reset_bar<<<1, 1>>>();
    scan_kernel<<<sgrid, SCAN_THREADS, SCAN_SMEM_BYTES>>>(w_hh0, b_hh0, 0);
    // layer 1
    gemm_xg<<<ggrid, 256>>>(nullptr, 1, Hc, w_ih1, b_ih1);
    reset_bar<<<1, 1>>>();
    scan_kernel<<<sgrid, SCAN_THREADS, SCAN_SMEM_BYTES>>>(w_hh1, b_hh1, 1);
    // layer 2
    gemm_xg<<<ggrid, 256>>>(nullptr, 2, Hc, w_ih2, b_ih2);
    reset_bar<<<1, 1>>>();
    scan_kernel<<<sgrid, SCAN_THREADS, SCAN_SMEM_BYTES>>>(w_hh2, b_hh2, 2);
    // head
    fc_kernel<<<64, 128>>>(fc1_w, fc1_b, fco_w, fco_b, out);
}

// round 2
// speedup vs baseline: 1.8436x; 1.8436x over previous
#include <cuda_runtime.h>
#include <cuda_bf16.h>
#include <math.h>

typedef unsigned long long ull;

// Problem constants
#define Bc 64
#define Tc 512
#define Ic 2048
#define Hc 256
#define Gc 768   // 3*H

// ---------------- device scratch (no allocations allowed) ----------------
__device__ float g_xg[(size_t)Bc * Tc * Gc];   // 96 MB, reused per layer
__device__ float g_y0[(size_t)Bc * Tc * Hc];   // layer0 output
__device__ float g_y1[(size_t)Bc * Tc * Hc];   // layer1 output
__device__ float g_y2[(size_t)Bc * Tc * Hc];   // layer2 output

// ---------------- packed f32x2 helpers ----------------
__device__ __forceinline__ ull pack2(float x, float y) {
    ull r; asm("mov.b64 %0, {%1, %2};" : "=l"(r) : "f"(x), "f"(y)); return r;
}
__device__ __forceinline__ void unpack2(ull v, float& x, float& y) {
    asm("mov.b64 {%0, %1}, %2;" : "=f"(x), "=f"(y) : "l"(v));
}
__device__ __forceinline__ ull fma2(ull a, ull b, ull c) {
    ull d; asm("fma.rn.f32x2 %0, %1, %2, %3;" : "=l"(d) : "l"(a), "l"(b), "l"(c)); return d;
}
__device__ __forceinline__ ull add2(ull a, ull b) {
    ull d; asm("add.rn.f32x2 %0, %1, %2;" : "=l"(d) : "l"(a), "l"(b)); return d;
}

__device__ __forceinline__ float sigmoidf_(float x) {
    return 1.0f / (1.0f + __expf(-x));
}

__device__ __forceinline__ unsigned smem_u32(const void* p) {
    return (unsigned)__cvta_generic_to_shared(p);
}

// ---------------- GEMM: C[m,g] = sum_k A[m,k] * W[g,k] + bias[g] ----------------
// M = Bc*Tc = 32768 (rows), N = 768, K in {2048, 256}. BM=BN=128, BK=16, 256 thr, 8x8/thread.
__global__ __launch_bounds__(256) void gemm_xg(const float* __restrict__ Aext, int src, int K,
                                               const float* __restrict__ W,
                                               const float* __restrict__ bias) {
    const float* A = (src == 0) ? Aext : (src == 1 ? g_y0 : g_y1);
    float* C = g_xg;
    __shared__ float As[16][128];
    __shared__ float Ws[16][128];
    int tid = threadIdx.x;
    int m0 = blockIdx.y * 128;
    int n0 = blockIdx.x * 128;
    int lr = tid >> 2;            // 0..63
    int lc = (tid & 3) << 2;      // 0,4,8,12
    int tx = tid & 15, ty = tid >> 4;

    ull acc[8][4];
#pragma unroll
    for (int i = 0; i < 8; i++)
#pragma unroll
        for (int j = 0; j < 4; j++) acc[i][j] = 0ULL;

    const float* Ap = A + (size_t)(m0 + lr) * K + lc;
    const float* Wp = W + (size_t)(n0 + lr) * K + lc;

    for (int k0 = 0; k0 < K; k0 += 16) {
        float4 a0 = *(const float4*)(Ap + k0);
        float4 a1 = *(const float4*)(Ap + (size_t)64 * K + k0);
        float4 w0 = *(const float4*)(Wp + k0);
        float4 w1 = *(const float4*)(Wp + (size_t)64 * K + k0);
        __syncthreads();
        As[lc + 0][lr] = a0.x; As[lc + 1][lr] = a0.y; As[lc + 2][lr] = a0.z; As[lc + 3][lr] = a0.w;
        As[lc + 0][lr + 64] = a1.x; As[lc + 1][lr + 64] = a1.y; As[lc + 2][lr + 64] = a1.z; As[lc + 3][lr + 64] = a1.w;
        Ws[lc + 0][lr] = w0.x; Ws[lc + 1][lr] = w0.y; Ws[lc + 2][lr] = w0.z; Ws[lc + 3][lr] = w0.w;
        Ws[lc + 0][lr + 64] = w1.x; Ws[lc + 1][lr + 64] = w1.y; Ws[lc + 2][lr + 64] = w1.z; Ws[lc + 3][lr + 64] = w1.w;
        __syncthreads();
#pragma unroll
        for (int kk = 0; kk < 16; kk++) {
            float4 av0 = *(const float4*)&As[kk][ty * 8];
            float4 av1 = *(const float4*)&As[kk][ty * 8 + 4];
            ulonglong2 b0 = *(const ulonglong2*)&Ws[kk][tx * 8];
            ulonglong2 b1 = *(const ulonglong2*)&Ws[kk][tx * 8 + 4];
            float a[8] = {av0.x, av0.y, av0.z, av0.w, av1.x, av1.y, av1.z, av1.w};
            ull bb[4] = {b0.x, b0.y, b1.x, b1.y};
#pragma unroll
            for (int i = 0; i < 8; i++) {
                ull ad = pack2(a[i], a[i]);
#pragma unroll
                for (int j = 0; j < 4; j++) acc[i][j] = fma2(ad, bb[j], acc[i][j]);
            }
        }
    }

    float bsv[8];
#pragma unroll
    for (int j = 0; j < 8; j++) bsv[j] = bias[n0 + tx * 8 + j];
#pragma unroll
    for (int i = 0; i < 8; i++) {
        float o[8];
        unpack2(acc[i][0], o[0], o[1]);
        unpack2(acc[i][1], o[2], o[3]);
        unpack2(acc[i][2], o[4], o[5]);
        unpack2(acc[i][3], o[6], o[7]);
        size_t row = (size_t)(m0 + ty * 8 + i) * Gc + n0 + tx * 8;
        float4 s0 = make_float4(o[0] + bsv[0], o[1] + bsv[1], o[2] + bsv[2], o[3] + bsv[3]);
        float4 s1 = make_float4(o[4] + bsv[4], o[5] + bsv[5], o[6] + bsv[6], o[7] + bsv[7]);
        *(float4*)&C[row] = s0;
        *(float4*)&C[row + 4] = s1;
    }
}

// ---------------- cluster-based persistent recurrent scan ----------------
// Grid (4, 32): 32 clusters of 4 CTAs. Cluster cy owns batches {2cy, 2cy+1}.
// CTA rank r owns gates {s*256 + 64r + j : s in 0..2, j in 0..63} (192 gate rows).
// w_hh slice lives in REGISTERS: 384 threads x 64 packed (w_c, w_c+1) ull = 128 regs.
// Thread t: colpair cp = t%96 (cols 2cp, 2cp+1), k-quarter kq = t/96 (k in [64kq, 64kq+64)).
// h kept in smem pre-duplicated as (h,h) ull; new h exchanged via st.shared::cluster.
#define SCAN_THREADS 384

__device__ __forceinline__ void cluster_sync_() {
    asm volatile("barrier.cluster.arrive.aligned;" ::: "memory");
    asm volatile("barrier.cluster.wait.aligned;" ::: "memory");
}

__global__ __launch_bounds__(SCAN_THREADS, 1) __cluster_dims__(4, 1, 1)
void scan_kernel(const float* __restrict__ w_hh,
                 const float* __restrict__ b_hh,
                 int layer) {
    __shared__ __align__(16) ull hdup[2][2][Hc];   // [buf][batch][k] = (h,h)   8 KB
    __shared__ __align__(16) ull part[8][96];      // [kq*2+b][cp] partials     6 KB
    __shared__ __align__(16) float gates[2][192];  // [batch][s*64+j]           1.5 KB
    __shared__ __align__(16) ull biasdup[96];      // (b_hh[c], b_hh[c+1])      768 B

    const float* xg = g_xg;
    float* yout = (layer == 0) ? g_y0 : (layer == 1 ? g_y1 : g_y2);

    const int tid  = threadIdx.x;
    const int rank = blockIdx.x;          // cluster rank 0..3
    const int B0   = blockIdx.y * 2;      // first batch of this cluster

    const int cp = tid % 96;              // column pair index
    const int kq = tid / 96;              // k quarter 0..3
    const int kbase = kq * 64;
    const int c0 = 2 * cp;
    const int s  = c0 >> 6;
    const int jl = c0 & 63;
    const int grow = s * 256 + 64 * rank + jl;  // global gate row of col c0

    // ---- one-time init ----
    if (tid < 96) {
        int cc0 = 2 * tid;
        int ss = cc0 >> 6, jj = cc0 & 63;
        int gr = ss * 256 + 64 * rank + jj;
        biasdup[tid] = pack2(b_hh[gr], b_hh[gr + 1]);
    }
    for (int idx = tid; idx < 2 * Hc; idx += SCAN_THREADS) {
        hdup[0][idx >> 8][idx & 255] = 0ULL;
    }

    // ---- load w slice into registers (pre-packed col pairs) ----
    ull wreg[64];
    {
        const float* w0p = w_hh + (size_t)grow * Hc + kbase;
        const float* w1p = w0p + Hc;
#pragma unroll
        for (int i = 0; i < 64; i++) wreg[i] = pack2(__ldg(w0p + i), __ldg(w1p + i));
    }
    __syncthreads();

    const unsigned hbase_u32[2] = { smem_u32(&hdup[0][0][0]), smem_u32(&hdup[1][0][0]) };

    for (int t = 0; t < Tc; t++) {
        const int p = t & 1;

        // ---- prefetch xg for the pointwise phase (hides DRAM under GEMM) ----
        float xr = 0.f, xz = 0.f, xn = 0.f;
        if (tid < 128) {
            int b = tid >> 6, j = tid & 63;
            const float* xp = xg + ((size_t)(B0 + b) * Tc + t) * Gc + 64 * rank + j;
            xr = __ldg(xp); xz = __ldg(xp + 256); xn = __ldg(xp + 512);
        }

        // ---- GEMM partial: cols (c0,c0+1), batches 0/1, k in [kbase, kbase+64) ----
        {
            const ull* h0 = &hdup[p][0][kbase];
            const ull* h1 = &hdup[p][1][kbase];
            ull a0 = 0ULL, a1 = 0ULL, bb0 = 0ULL, bb1 = 0ULL;
#pragma unroll
            for (int i = 0; i < 64; i += 2) {
                ulonglong2 ha = *(const ulonglong2*)(h0 + i);
                ulonglong2 hb = *(const ulonglong2*)(h1 + i);
                a0  = fma2(ha.x, wreg[i],     a0);
                bb0 = fma2(hb.x, wreg[i],     bb0);
                a1  = fma2(ha.y, wreg[i + 1], a1);
                bb1 = fma2(hb.y, wreg[i + 1], bb1);
            }
            part[kq * 2 + 0][cp] = add2(a0, a1);
            part[kq * 2 + 1][cp] = add2(bb0, bb1);
        }
        __syncthreads();

        // ---- reduce across 4 k-quarters, add bias ----
        if (tid < 192) {
            int b = tid / 96, c = tid % 96;
            ull v = add2(add2(part[0 * 2 + b][c], part[1 * 2 + b][c]),
                         add2(part[2 * 2 + b][c], part[3 * 2 + b][c]));
            v = add2(v, biasdup[c]);
            *(ull*)&gates[b][2 * c] = v;
        }
        __syncthreads();

        // ---- pointwise GRU update for own 64 units x 2 batches ----
        if (tid < 128) {
            int b = tid >> 6, j = tid & 63;
            int slot = 64 * rank + j;
            float hr = gates[b][j];
            float hz = gates[b][64 + j];
            float hn = gates[b][128 + j];
            float hp, dummy;
            unpack2(hdup[p][b][slot], hp, dummy);
            float r = sigmoidf_(xr + hr);
            float z = sigmoidf_(xz + hz);
            float n = tanhf(xn + r * hn);
            float hnew = fmaf(z, hp - n, n);
            ull hd = pack2(hnew, hnew);
            // local write + broadcast to 3 peers (double-buffered slot)
            hdup[p ^ 1][b][slot] = hd;
            unsigned laddr = hbase_u32[p ^ 1] + (unsigned)((b * Hc + slot) * 8);
#pragma unroll
            for (int pr = 1; pr < 4; pr++) {
                unsigned r2 = (rank + pr) & 3;
                unsigned raddr;
                asm("mapa.shared::cluster.u32 %0, %1, %2;" : "=r"(raddr) : "r"(laddr), "r"(r2));
                asm volatile("st.shared::cluster.b64 [%0], %1;" :: "r"(raddr), "l"(hd) : "memory");
            }
            yout[((size_t)(B0 + b) * Tc + t) * Hc + slot] = hnew;
        }

        // ---- cluster barrier: peers' h writes visible for next step ----
        cluster_sync_();
    }
}

// ---------------- FC head ----------------
__global__ __launch_bounds__(128) void fc_kernel(const float* __restrict__ fc1_w,
                                                 const float* __restrict__ fc1_b,
                                                 const float* __restrict__ fco_w,
                                                 const float* __restrict__ fco_b,
                                                 float* __restrict__ out) {
    int b = blockIdx.x;
    int f = threadIdx.x;
    const float* last = g_y2 + ((size_t)b * Tc + (Tc - 1)) * Hc;
    __shared__ float ls[256];
    for (int k = f; k < 256; k += 128) ls[k] = last[k];
    __syncthreads();
    float acc = fc1_b[f];
    const float* wr = fc1_w + (size_t)f * 256;
#pragma unroll 8
    for (int k = 0; k < 256; k++) acc = fmaf(ls[k], wr[k], acc);
    float z = fmaxf(acc, 0.0f);
    float v = z * fco_w[f];
#pragma unroll
    for (int o = 16; o > 0; o >>= 1) v += __shfl_xor_sync(0xffffffffu, v, o);
    __shared__ float ws[4];
    if ((f & 31) == 0) ws[f >> 5] = v;
    __syncthreads();
    if (f == 0) out[b] = ws[0] + ws[1] + ws[2] + ws[3] + fco_b[0];
}

// ---------------- launch ----------------
extern "C" void kernel_launch(void* const* d_in, const int* in_sizes, int n_in,
                              void* d_out, int out_size) {
    const float* x     = (const float*)d_in[0];
    const float* w_ih0 = (const float*)d_in[1];
    const float* w_hh0 = (const float*)d_in[2];
    const float* b_ih0 = (const float*)d_in[3];
    const float* b_hh0 = (const float*)d_in[4];
    const float* w_ih1 = (const float*)d_in[5];
    const float* w_hh1 = (const float*)d_in[6];
    const float* b_ih1 = (const float*)d_in[7];
    const float* b_hh1 = (const float*)d_in[8];
    const float* w_ih2 = (const float*)d_in[9];
    const float* w_hh2 = (const float*)d_in[10];
    const float* b_ih2 = (const float*)d_in[11];
    const float* b_hh2 = (const float*)d_in[12];
    const float* fc1_w = (const float*)d_in[13];
    const float* fc1_b = (const float*)d_in[14];
    const float* fco_w = (const float*)d_in[15];
    const float* fco_b = (const float*)d_in[16];
    float* out = (float*)d_out;

    dim3 ggrid(6, 256);      // N tiles x M tiles
    dim3 sgrid(4, 32);       // 32 clusters x 4 CTAs (cluster dims static)

    // layer 0
    gemm_xg<<<ggrid, 256>>>(x, 0, Ic, w_ih0, b_ih0);
    scan_kernel<<<sgrid, SCAN_THREADS>>>(w_hh0, b_hh0, 0);
    // layer 1
    gemm_xg<<<ggrid, 256>>>(nullptr, 1, Hc, w_ih1, b_ih1);
    scan_kernel<<<sgrid, SCAN_THREADS>>>(w_hh1, b_hh1, 1);
    // layer 2
    gemm_xg<<<ggrid, 256>>>(nullptr, 2, Hc, w_ih2, b_ih2);
    scan_kernel<<<sgrid, SCAN_THREADS>>>(w_hh2, b_hh2, 2);
    // head
    fc_kernel<<<64, 128>>>(fc1_w, fc1_b, fco_w, fco_b, out);
}

// round 6
// speedup vs baseline: 2.3262x; 1.2617x over previous
#include <cuda_runtime.h>
#include <cuda_bf16.h>
#include <stdint.h>
#include <math.h>

typedef unsigned long long ull;

// Problem constants
#define Bc 64
#define Tc 512
#define Ic 2048
#define Hc 256
#define Gc 768   // 3*H
#define Mr ((size_t)Bc * Tc)   // 32768 rows

// ---------------- device scratch (no allocations allowed) ----------------
__device__ float g_xg[Mr * Gc];     // xg buffer, reused per layer
__device__ float g_y0[Mr * Hc];
__device__ float g_y1[Mr * Hc];
__device__ float g_y2[Mr * Hc];

// ---------------- packed f32x2 helpers ----------------
__device__ __forceinline__ ull pack2(float x, float y) {
    ull r; asm("mov.b64 %0, {%1, %2};" : "=l"(r) : "f"(x), "f"(y)); return r;
}
__device__ __forceinline__ void unpack2(ull v, float& x, float& y) {
    asm("mov.b64 {%0, %1}, %2;" : "=f"(x), "=f"(y) : "l"(v));
}
__device__ __forceinline__ ull fma2(ull a, ull b, ull c) {
    ull d; asm("fma.rn.f32x2 %0, %1, %2, %3;" : "=l"(d) : "l"(a), "l"(b), "l"(c)); return d;
}
__device__ __forceinline__ ull add2(ull a, ull b) {
    ull d; asm("add.rn.f32x2 %0, %1, %2;" : "=l"(d) : "l"(a), "l"(b)); return d;
}
__device__ __forceinline__ float sigmoidf_(float x) { return 1.0f / (1.0f + __expf(-x)); }
__device__ __forceinline__ unsigned smem_u32(const void* p) {
    return (unsigned)__cvta_generic_to_shared(p);
}

// ---------------- mma.sync helpers (base-target sm_80+ instructions) ----------------
__device__ __forceinline__ void ldsm_x4(uint32_t& r0, uint32_t& r1, uint32_t& r2, uint32_t& r3,
                                        uint32_t addr) {
    asm volatile("ldmatrix.sync.aligned.m8n8.x4.shared.b16 {%0,%1,%2,%3}, [%4];"
                 : "=r"(r0), "=r"(r1), "=r"(r2), "=r"(r3) : "r"(addr));
}
__device__ __forceinline__ void mma_bf16(float& d0, float& d1, float& d2, float& d3,
                                         uint32_t a0, uint32_t a1, uint32_t a2, uint32_t a3,
                                         uint32_t b0, uint32_t b1) {
    asm volatile(
        "mma.sync.aligned.m16n8k16.row.col.f32.bf16.bf16.f32 "
        "{%0,%1,%2,%3},{%4,%5,%6,%7},{%8,%9},{%0,%1,%2,%3};"
        : "+f"(d0), "+f"(d1), "+f"(d2), "+f"(d3)
        : "r"(a0), "r"(a1), "r"(a2), "r"(a3), "r"(b0), "r"(b1));
}
__device__ __forceinline__ void cvt_hilo(float4 v, ull& hi, ull& lo) {
    __nv_bfloat16 h0 = __float2bfloat16(v.x), h1 = __float2bfloat16(v.y);
    __nv_bfloat16 h2 = __float2bfloat16(v.z), h3 = __float2bfloat16(v.w);
    __nv_bfloat16 l0 = __float2bfloat16(v.x - __bfloat162float(h0));
    __nv_bfloat16 l1 = __float2bfloat16(v.y - __bfloat162float(h1));
    __nv_bfloat16 l2 = __float2bfloat16(v.z - __bfloat162float(h2));
    __nv_bfloat16 l3 = __float2bfloat16(v.w - __bfloat162float(h3));
    hi = (ull)__bfloat16_as_ushort(h0) | ((ull)__bfloat16_as_ushort(h1) << 16)
       | ((ull)__bfloat16_as_ushort(h2) << 32) | ((ull)__bfloat16_as_ushort(h3) << 48);
    lo = (ull)__bfloat16_as_ushort(l0) | ((ull)__bfloat16_as_ushort(l1) << 16)
       | ((ull)__bfloat16_as_ushort(l2) << 32) | ((ull)__bfloat16_as_ushort(l3) << 48);
}

// ---------------- HMMA GEMM: g_xg[m,n] = A[m,:] . W[n,:] + bias[n] ----------------
// BM=BN=128, BK=32, 256 threads (8 warps, warp tile 32x64).
// Split-bf16 3-term: acc += Ahi*Whi + Ahi*Wlo + Alo*Whi (fp32 accumulate).
// SMEM: per stage 4 tiles of 128 x 32 bf16 (rows padded to 40 elems).
#define LDAp 40
#define TILE_E (128 * LDAp)                 // elems per tile
#define STAGE_E (4 * TILE_E)                // Ahi, Alo, Whi, Wlo
#define GEMM_SMEM (2 * STAGE_E * 2)         // bytes (2 stages, bf16)

__global__ __launch_bounds__(256, 1)
void gemm_tc(const float* __restrict__ A, const float* __restrict__ W,
             const float* __restrict__ bias, int K) {
    extern __shared__ __nv_bfloat16 sm[];
    const uint32_t sbase = smem_u32(sm);
    const int tid = threadIdx.x, lane = tid & 31, wid = tid >> 5;
    const int wm = wid & 3, wn = wid >> 2;
    const int m0 = blockIdx.y * 128, n0 = blockIdx.x * 128;
    const int nkb = K >> 5;

    // GMEM staging: 4 float4 each for A and W per chunk
    float4 ra[4], rw[4];
    // thread's tile coords for loads: f = i*256+tid; r=f>>3, c8=f&7
#pragma unroll
    for (int i = 0; i < 4; i++) {
        int f = i * 256 + tid, r = f >> 3, c8 = f & 7;
        ra[i] = *(const float4*)(A + (size_t)(m0 + r) * K + c8 * 4);
        rw[i] = *(const float4*)(W + (size_t)(n0 + r) * K + c8 * 4);
    }

    // per-thread ldmatrix base offsets (elems): row = base + (lane&15), col = 8*(lane>>4)
    const int lrow = lane & 15, lcol = (lane >> 4) * 8;
    const uint32_t offA = ((wm * 32 + lrow) * LDAp + lcol) * 2;
    const uint32_t offB = ((wn * 64 + lrow) * LDAp + lcol) * 2;

    float acc[2][8][4];
#pragma unroll
    for (int i = 0; i < 2; i++)
#pragma unroll
        for (int j = 0; j < 8; j++)
#pragma unroll
            for (int q = 0; q < 4; q++) acc[i][j][q] = 0.0f;

    for (int kb = 0; kb < nkb; kb++) {
        const int p = kb & 1;
        __nv_bfloat16* st = sm + p * STAGE_E;
        // convert + store staged regs
#pragma unroll
        for (int i = 0; i < 4; i++) {
            int f = i * 256 + tid, r = f >> 3, c8 = f & 7;
            ull hiA, loA, hiW, loW;
            cvt_hilo(ra[i], hiA, loA);
            cvt_hilo(rw[i], hiW, loW);
            int e = r * LDAp + c8 * 4;
            *(ull*)(st + e)              = hiA;
            *(ull*)(st + TILE_E + e)     = loA;
            *(ull*)(st + 2 * TILE_E + e) = hiW;
            *(ull*)(st + 3 * TILE_E + e) = loW;
        }
        __syncthreads();
        // prefetch next chunk
        if (kb + 1 < nkb) {
            int kc = (kb + 1) * 32;
#pragma unroll
            for (int i = 0; i < 4; i++) {
                int f = i * 256 + tid, r = f >> 3, c8 = f & 7;
                ra[i] = *(const float4*)(A + (size_t)(m0 + r) * K + kc + c8 * 4);
                rw[i] = *(const float4*)(W + (size_t)(n0 + r) * K + kc + c8 * 4);
            }
        }
        // compute on stage p
        const uint32_t bAhi = sbase + (uint32_t)(p * STAGE_E) * 2 + offA;
        const uint32_t bAlo = bAhi + TILE_E * 2;
        const uint32_t bWhi = sbase + (uint32_t)(p * STAGE_E) * 2 + 2 * TILE_E * 2 + offB;
        const uint32_t bWlo = bWhi + TILE_E * 2;
#pragma unroll
        for (int ks = 0; ks < 2; ks++) {
            const uint32_t ko = ks * 32;  // 16 elems * 2B
            uint32_t ah[2][4], al[2][4];
#pragma unroll
            for (int ma = 0; ma < 2; ma++) {
                ldsm_x4(ah[ma][0], ah[ma][1], ah[ma][2], ah[ma][3],
                        bAhi + ko + ma * 16 * LDAp * 2);
                ldsm_x4(al[ma][0], al[ma][1], al[ma][2], al[ma][3],
                        bAlo + ko + ma * 16 * LDAp * 2);
            }
            uint32_t wh[4][4], wl[4][4];
#pragma unroll
            for (int pa = 0; pa < 4; pa++) {
                ldsm_x4(wh[pa][0], wh[pa][1], wh[pa][2], wh[pa][3],
                        bWhi + ko + pa * 16 * LDAp * 2);
                ldsm_x4(wl[pa][0], wl[pa][1], wl[pa][2], wl[pa][3],
                        bWlo + ko + pa * 16 * LDAp * 2);
            }
#pragma unroll
            for (int ma = 0; ma < 2; ma++) {
#pragma unroll
                for (int na = 0; na < 8; na++) {
                    const int pa = na >> 1, hf = na & 1;
                    float* d = acc[ma][na];
                    mma_bf16(d[0], d[1], d[2], d[3],
                             ah[ma][0], ah[ma][1], ah[ma][2], ah[ma][3],
                             wh[pa][hf], wh[pa][hf + 2]);
                    mma_bf16(d[0], d[1], d[2], d[3],
                             ah[ma][0], ah[ma][1], ah[ma][2], ah[ma][3],
                             wl[pa][hf], wl[pa][hf + 2]);
                    mma_bf16(d[0], d[1], d[2], d[3],
                             al[ma][0], al[ma][1], al[ma][2], al[ma][3],
                             wh[pa][hf], wh[pa][hf + 2]);
                }
            }
        }
        __syncthreads();
    }

    // epilogue: write acc + bias directly to g_xg
#pragma unroll
    for (int ma = 0; ma < 2; ma++) {
#pragma unroll
        for (int na = 0; na < 8; na++) {
            int row = m0 + wm * 32 + ma * 16 + (lane >> 2);
            int col = n0 + wn * 64 + na * 8 + (lane & 3) * 2;
            float b0 = __ldg(bias + col), b1 = __ldg(bias + col + 1);
            float* d = acc[ma][na];
            *(float2*)&g_xg[(size_t)row * Gc + col] = make_float2(d[0] + b0, d[1] + b1);
            *(float2*)&g_xg[(size_t)(row + 8) * Gc + col] = make_float2(d[2] + b0, d[3] + b1);
        }
    }
}

// ---------------- cluster-based persistent recurrent scan (unchanged from R2) ----------------
#define SCAN_THREADS 384

__device__ __forceinline__ void cluster_sync_() {
    asm volatile("barrier.cluster.arrive.aligned;" ::: "memory");
    asm volatile("barrier.cluster.wait.aligned;" ::: "memory");
}

__global__ __launch_bounds__(SCAN_THREADS, 1) __cluster_dims__(4, 1, 1)
void scan_kernel(const float* __restrict__ w_hh,
                 const float* __restrict__ b_hh,
                 int layer) {
    __shared__ __align__(16) ull hdup[2][2][Hc];
    __shared__ __align__(16) ull part[8][96];
    __shared__ __align__(16) float gates[2][192];
    __shared__ __align__(16) ull biasdup[96];

    const float* xg = g_xg;
    float* yout = (layer == 0) ? g_y0 : (layer == 1 ? g_y1 : g_y2);

    const int tid  = threadIdx.x;
    const int rank = blockIdx.x;
    const int B0   = blockIdx.y * 2;

    const int cp = tid % 96;
    const int kq = tid / 96;
    const int kbase = kq * 64;
    const int c0 = 2 * cp;
    const int s  = c0 >> 6;
    const int jl = c0 & 63;
    const int grow = s * 256 + 64 * rank + jl;

    if (tid < 96) {
        int cc0 = 2 * tid;
        int ss = cc0 >> 6, jj = cc0 & 63;
        int gr = ss * 256 + 64 * rank + jj;
        biasdup[tid] = pack2(b_hh[gr], b_hh[gr + 1]);
    }
    for (int idx = tid; idx < 2 * Hc; idx += SCAN_THREADS) {
        hdup[0][idx >> 8][idx & 255] = 0ULL;
    }

    ull wreg[64];
    {
        const float* w0p = w_hh + (size_t)grow * Hc + kbase;
        const float* w1p = w0p + Hc;
#pragma unroll
        for (int i = 0; i < 64; i++) wreg[i] = pack2(__ldg(w0p + i), __ldg(w1p + i));
    }
    __syncthreads();

    const unsigned hbase_u32[2] = { smem_u32(&hdup[0][0][0]), smem_u32(&hdup[1][0][0]) };

    for (int t = 0; t < Tc; t++) {
        const int p = t & 1;

        float xr = 0.f, xz = 0.f, xn = 0.f;
        if (tid < 128) {
            int b = tid >> 6, j = tid & 63;
            const float* xp = xg + ((size_t)(B0 + b) * Tc + t) * Gc + 64 * rank + j;
            xr = __ldg(xp); xz = __ldg(xp + 256); xn = __ldg(xp + 512);
        }

        {
            const ull* h0 = &hdup[p][0][kbase];
            const ull* h1 = &hdup[p][1][kbase];
            ull a0 = 0ULL, a1 = 0ULL, bb0 = 0ULL, bb1 = 0ULL;
#pragma unroll
            for (int i = 0; i < 64; i += 2) {
                ulonglong2 ha = *(const ulonglong2*)(h0 + i);
                ulonglong2 hb = *(const ulonglong2*)(h1 + i);
                a0  = fma2(ha.x, wreg[i],     a0);
                bb0 = fma2(hb.x, wreg[i],     bb0);
                a1  = fma2(ha.y, wreg[i + 1], a1);
                bb1 = fma2(hb.y, wreg[i + 1], bb1);
            }
            part[kq * 2 + 0][cp] = add2(a0, a1);
            part[kq * 2 + 1][cp] = add2(bb0, bb1);
        }
        __syncthreads();

        if (tid < 192) {
            int b = tid / 96, c = tid % 96;
            ull v = add2(add2(part[0 * 2 + b][c], part[1 * 2 + b][c]),
                         add2(part[2 * 2 + b][c], part[3 * 2 + b][c]));
            v = add2(v, biasdup[c]);
            *(ull*)&gates[b][2 * c] = v;
        }
        __syncthreads();

        if (tid < 128) {
            int b = tid >> 6, j = tid & 63;
            int slot = 64 * rank + j;
            float hr = gates[b][j];
            float hz = gates[b][64 + j];
            float hn = gates[b][128 + j];
            float hp, dummy;
            unpack2(hdup[p][b][slot], hp, dummy);
            float r = sigmoidf_(xr + hr);
            float z = sigmoidf_(xz + hz);
            float n = tanhf(xn + r * hn);
            float hnew = fmaf(z, hp - n, n);
            ull hd = pack2(hnew, hnew);
            hdup[p ^ 1][b][slot] = hd;
            unsigned laddr = hbase_u32[p ^ 1] + (unsigned)((b * Hc + slot) * 8);
#pragma unroll
            for (int pr = 1; pr < 4; pr++) {
                unsigned r2 = (rank + pr) & 3;
                unsigned raddr;
                asm("mapa.shared::cluster.u32 %0, %1, %2;" : "=r"(raddr) : "r"(laddr), "r"(r2));
                asm volatile("st.shared::cluster.b64 [%0], %1;" :: "r"(raddr), "l"(hd) : "memory");
            }
            yout[((size_t)(B0 + b) * Tc + t) * Hc + slot] = hnew;
        }

        cluster_sync_();
    }
}

// ---------------- FC head ----------------
__global__ __launch_bounds__(128) void fc_kernel(const float* __restrict__ fc1_w,
                                                 const float* __restrict__ fc1_b,
                                                 const float* __restrict__ fco_w,
                                                 const float* __restrict__ fco_b,
                                                 float* __restrict__ out) {
    int b = blockIdx.x;
    int f = threadIdx.x;
    const float* last = g_y2 + ((size_t)b * Tc + (Tc - 1)) * Hc;
    __shared__ float ls[256];
    for (int k = f; k < 256; k += 128) ls[k] = last[k];
    __syncthreads();
    float acc = fc1_b[f];
    const float* wr = fc1_w + (size_t)f * 256;
#pragma unroll 8
    for (int k = 0; k < 256; k++) acc = fmaf(ls[k], wr[k], acc);
    float z = fmaxf(acc, 0.0f);
    float v = z * fco_w[f];
#pragma unroll
    for (int o = 16; o > 0; o >>= 1) v += __shfl_xor_sync(0xffffffffu, v, o);
    __shared__ float ws[4];
    if ((f & 31) == 0) ws[f >> 5] = v;
    __syncthreads();
    if (f == 0) out[b] = ws[0] + ws[1] + ws[2] + ws[3] + fco_b[0];
}

// ---------------- launch ----------------
extern "C" void kernel_launch(void* const* d_in, const int* in_sizes, int n_in,
                              void* d_out, int out_size) {
    const float* x     = (const float*)d_in[0];
    const float* w_ih0 = (const float*)d_in[1];
    const float* w_hh0 = (const float*)d_in[2];
    const float* b_ih0 = (const float*)d_in[3];
    const float* b_hh0 = (const float*)d_in[4];
    const float* w_ih1 = (const float*)d_in[5];
    const float* w_hh1 = (const float*)d_in[6];
    const float* b_ih1 = (const float*)d_in[7];
    const float* b_hh1 = (const float*)d_in[8];
    const float* w_ih2 = (const float*)d_in[9];
    const float* w_hh2 = (const float*)d_in[10];
    const float* b_ih2 = (const float*)d_in[11];
    const float* b_hh2 = (const float*)d_in[12];
    const float* fc1_w = (const float*)d_in[13];
    const float* fc1_b = (const float*)d_in[14];
    const float* fco_w = (const float*)d_in[15];
    const float* fco_b = (const float*)d_in[16];
    float* out = (float*)d_out;

    cudaFuncSetAttribute(gemm_tc, cudaFuncAttributeMaxDynamicSharedMemorySize, GEMM_SMEM);

    float* y0p; cudaGetSymbolAddress((void**)&y0p, g_y0);
    float* y1p; cudaGetSymbolAddress((void**)&y1p, g_y1);

    dim3 ggrid(6, 256);      // N tiles x M tiles
    dim3 sgrid(4, 32);       // 32 clusters x 4 CTAs

    // layer 0
    gemm_tc<<<ggrid, 256, GEMM_SMEM>>>(x, w_ih0, b_ih0, Ic);
    scan_kernel<<<sgrid, SCAN_THREADS>>>(w_hh0, b_hh0, 0);
    // layer 1
    gemm_tc<<<ggrid, 256, GEMM_SMEM>>>(y0p, w_ih1, b_ih1, Hc);
    scan_kernel<<<sgrid, SCAN_THREADS>>>(w_hh1, b_hh1, 1);
    // layer 2
    gemm_tc<<<ggrid, 256, GEMM_SMEM>>>(y1p, w_ih2, b_ih2, Hc);
    scan_kernel<<<sgrid, SCAN_THREADS>>>(w_hh2, b_hh2, 2);
    // head
    fc_kernel<<<64, 128>>>(fc1_w, fc1_b, fco_w, fco_b, out);
}

// round 7
// speedup vs baseline: 2.3271x; 1.0004x over previous
#include <cuda_runtime.h>
#include <cuda_bf16.h>
#include <stdint.h>
#include <math.h>

typedef unsigned long long ull;

// Problem constants
#define Bc 64
#define Tc 512
#define Ic 2048
#define Hc 256
#define Gc 768   // 3*H
#define Mr ((size_t)Bc * Tc)   // 32768 rows

// ---------------- device scratch (no allocations allowed) ----------------
__device__ float g_xg[Mr * Gc];     // xg buffer, reused per layer
__device__ float g_y0[Mr * Hc];
__device__ float g_y1[Mr * Hc];
__device__ float g_y2[Mr * Hc];

// ---------------- packed f32x2 helpers ----------------
__device__ __forceinline__ ull pack2(float x, float y) {
    ull r; asm("mov.b64 %0, {%1, %2};" : "=l"(r) : "f"(x), "f"(y)); return r;
}
__device__ __forceinline__ void unpack2(ull v, float& x, float& y) {
    asm("mov.b64 {%0, %1}, %2;" : "=f"(x), "=f"(y) : "l"(v));
}
__device__ __forceinline__ ull fma2(ull a, ull b, ull c) {
    ull d; asm("fma.rn.f32x2 %0, %1, %2, %3;" : "=l"(d) : "l"(a), "l"(b), "l"(c)); return d;
}
__device__ __forceinline__ ull add2(ull a, ull b) {
    ull d; asm("add.rn.f32x2 %0, %1, %2;" : "=l"(d) : "l"(a), "l"(b)); return d;
}
__device__ __forceinline__ float sigmoidf_(float x) { return 1.0f / (1.0f + __expf(-x)); }
__device__ __forceinline__ unsigned smem_u32(const void* p) {
    return (unsigned)__cvta_generic_to_shared(p);
}

// ---------------- mma.sync helpers (base-target sm_80+ instructions) ----------------
__device__ __forceinline__ void ldsm_x4(uint32_t& r0, uint32_t& r1, uint32_t& r2, uint32_t& r3,
                                        uint32_t addr) {
    asm volatile("ldmatrix.sync.aligned.m8n8.x4.shared.b16 {%0,%1,%2,%3}, [%4];"
                 : "=r"(r0), "=r"(r1), "=r"(r2), "=r"(r3) : "r"(addr));
}
__device__ __forceinline__ void mma_bf16(float& d0, float& d1, float& d2, float& d3,
                                         uint32_t a0, uint32_t a1, uint32_t a2, uint32_t a3,
                                         uint32_t b0, uint32_t b1) {
    asm volatile(
        "mma.sync.aligned.m16n8k16.row.col.f32.bf16.bf16.f32 "
        "{%0,%1,%2,%3},{%4,%5,%6,%7},{%8,%9},{%0,%1,%2,%3};"
        : "+f"(d0), "+f"(d1), "+f"(d2), "+f"(d3)
        : "r"(a0), "r"(a1), "r"(a2), "r"(a3), "r"(b0), "r"(b1));
}
__device__ __forceinline__ void cvt_hilo(float4 v, ull& hi, ull& lo) {
    __nv_bfloat16 h0 = __float2bfloat16(v.x), h1 = __float2bfloat16(v.y);
    __nv_bfloat16 h2 = __float2bfloat16(v.z), h3 = __float2bfloat16(v.w);
    __nv_bfloat16 l0 = __float2bfloat16(v.x - __bfloat162float(h0));
    __nv_bfloat16 l1 = __float2bfloat16(v.y - __bfloat162float(h1));
    __nv_bfloat16 l2 = __float2bfloat16(v.z - __bfloat162float(h2));
    __nv_bfloat16 l3 = __float2bfloat16(v.w - __bfloat162float(h3));
    hi = (ull)__bfloat16_as_ushort(h0) | ((ull)__bfloat16_as_ushort(h1) << 16)
       | ((ull)__bfloat16_as_ushort(h2) << 32) | ((ull)__bfloat16_as_ushort(h3) << 48);
    lo = (ull)__bfloat16_as_ushort(l0) | ((ull)__bfloat16_as_ushort(l1) << 16)
       | ((ull)__bfloat16_as_ushort(l2) << 32) | ((ull)__bfloat16_as_ushort(l3) << 48);
}

// ---------------- HMMA GEMM: g_xg[m,n] = A[m,:] . W[n,:] + bias[n] ----------------
// BM=BN=128, BK=32, 256 threads (8 warps, warp tile 32x64).
// Split-bf16 3-term: acc += Ahi*Whi + Ahi*Wlo + Alo*Whi (fp32 accumulate).
// SMEM: per stage 4 tiles of 128 x 32 bf16 (rows padded to 40 elems).
#define LDAp 40
#define TILE_E (128 * LDAp)                 // elems per tile
#define STAGE_E (4 * TILE_E)                // Ahi, Alo, Whi, Wlo
#define GEMM_SMEM (2 * STAGE_E * 2)         // bytes (2 stages, bf16)

__global__ __launch_bounds__(256, 1)
void gemm_tc(const float* __restrict__ A, const float* __restrict__ W,
             const float* __restrict__ bias, int K) {
    extern __shared__ __nv_bfloat16 sm[];
    const uint32_t sbase = smem_u32(sm);
    const int tid = threadIdx.x, lane = tid & 31, wid = tid >> 5;
    const int wm = wid & 3, wn = wid >> 2;
    const int m0 = blockIdx.y * 128, n0 = blockIdx.x * 128;
    const int nkb = K >> 5;

    // GMEM staging: 4 float4 each for A and W per chunk
    float4 ra[4], rw[4];
    // thread's tile coords for loads: f = i*256+tid; r=f>>3, c8=f&7
#pragma unroll
    for (int i = 0; i < 4; i++) {
        int f = i * 256 + tid, r = f >> 3, c8 = f & 7;
        ra[i] = *(const float4*)(A + (size_t)(m0 + r) * K + c8 * 4);
        rw[i] = *(const float4*)(W + (size_t)(n0 + r) * K + c8 * 4);
    }

    // per-thread ldmatrix base offsets (elems): row = base + (lane&15), col = 8*(lane>>4)
    const int lrow = lane & 15, lcol = (lane >> 4) * 8;
    const uint32_t offA = ((wm * 32 + lrow) * LDAp + lcol) * 2;
    const uint32_t offB = ((wn * 64 + lrow) * LDAp + lcol) * 2;

    float acc[2][8][4];
#pragma unroll
    for (int i = 0; i < 2; i++)
#pragma unroll
        for (int j = 0; j < 8; j++)
#pragma unroll
            for (int q = 0; q < 4; q++) acc[i][j][q] = 0.0f;

    for (int kb = 0; kb < nkb; kb++) {
        const int p = kb & 1;
        __nv_bfloat16* st = sm + p * STAGE_E;
        // convert + store staged regs
#pragma unroll
        for (int i = 0; i < 4; i++) {
            int f = i * 256 + tid, r = f >> 3, c8 = f & 7;
            ull hiA, loA, hiW, loW;
            cvt_hilo(ra[i], hiA, loA);
            cvt_hilo(rw[i], hiW, loW);
            int e = r * LDAp + c8 * 4;
            *(ull*)(st + e)              = hiA;
            *(ull*)(st + TILE_E + e)     = loA;
            *(ull*)(st + 2 * TILE_E + e) = hiW;
            *(ull*)(st + 3 * TILE_E + e) = loW;
        }
        __syncthreads();
        // prefetch next chunk
        if (kb + 1 < nkb) {
            int kc = (kb + 1) * 32;
#pragma unroll
            for (int i = 0; i < 4; i++) {
                int f = i * 256 + tid, r = f >> 3, c8 = f & 7;
                ra[i] = *(const float4*)(A + (size_t)(m0 + r) * K + kc + c8 * 4);
                rw[i] = *(const float4*)(W + (size_t)(n0 + r) * K + kc + c8 * 4);
            }
        }
        // compute on stage p
        const uint32_t bAhi = sbase + (uint32_t)(p * STAGE_E) * 2 + offA;
        const uint32_t bAlo = bAhi + TILE_E * 2;
        const uint32_t bWhi = sbase + (uint32_t)(p * STAGE_E) * 2 + 2 * TILE_E * 2 + offB;
        const uint32_t bWlo = bWhi + TILE_E * 2;
#pragma unroll
        for (int ks = 0; ks < 2; ks++) {
            const uint32_t ko = ks * 32;  // 16 elems * 2B
            uint32_t ah[2][4], al[2][4];
#pragma unroll
            for (int ma = 0; ma < 2; ma++) {
                ldsm_x4(ah[ma][0], ah[ma][1], ah[ma][2], ah[ma][3],
                        bAhi + ko + ma * 16 * LDAp * 2);
                ldsm_x4(al[ma][0], al[ma][1], al[ma][2], al[ma][3],
                        bAlo + ko + ma * 16 * LDAp * 2);
            }
            uint32_t wh[4][4], wl[4][4];
#pragma unroll
            for (int pa = 0; pa < 4; pa++) {
                ldsm_x4(wh[pa][0], wh[pa][1], wh[pa][2], wh[pa][3],
                        bWhi + ko + pa * 16 * LDAp * 2);
                ldsm_x4(wl[pa][0], wl[pa][1], wl[pa][2], wl[pa][3],
                        bWlo + ko + pa * 16 * LDAp * 2);
            }
#pragma unroll
            for (int ma = 0; ma < 2; ma++) {
#pragma unroll
                for (int na = 0; na < 8; na++) {
                    const int pa = na >> 1, hf = na & 1;
                    float* d = acc[ma][na];
                    mma_bf16(d[0], d[1], d[2], d[3],
                             ah[ma][0], ah[ma][1], ah[ma][2], ah[ma][3],
                             wh[pa][hf], wh[pa][hf + 2]);
                    mma_bf16(d[0], d[1], d[2], d[3],
                             ah[ma][0], ah[ma][1], ah[ma][2], ah[ma][3],
                             wl[pa][hf], wl[pa][hf + 2]);
                    mma_bf16(d[0], d[1], d[2], d[3],
                             al[ma][0], al[ma][1], al[ma][2], al[ma][3],
                             wh[pa][hf], wh[pa][hf + 2]);
                }
            }
        }
        __syncthreads();
    }

    // epilogue: write acc + bias directly to g_xg
#pragma unroll
    for (int ma = 0; ma < 2; ma++) {
#pragma unroll
        for (int na = 0; na < 8; na++) {
            int row = m0 + wm * 32 + ma * 16 + (lane >> 2);
            int col = n0 + wn * 64 + na * 8 + (lane & 3) * 2;
            float b0 = __ldg(bias + col), b1 = __ldg(bias + col + 1);
            float* d = acc[ma][na];
            *(float2*)&g_xg[(size_t)row * Gc + col] = make_float2(d[0] + b0, d[1] + b1);
            *(float2*)&g_xg[(size_t)(row + 8) * Gc + col] = make_float2(d[2] + b0, d[3] + b1);
        }
    }
}

// ---------------- cluster-based persistent recurrent scan (unchanged from R2) ----------------
#define SCAN_THREADS 384

__device__ __forceinline__ void cluster_sync_() {
    asm volatile("barrier.cluster.arrive.aligned;" ::: "memory");
    asm volatile("barrier.cluster.wait.aligned;" ::: "memory");
}

__global__ __launch_bounds__(SCAN_THREADS, 1) __cluster_dims__(4, 1, 1)
void scan_kernel(const float* __restrict__ w_hh,
                 const float* __restrict__ b_hh,
                 int layer) {
    __shared__ __align__(16) ull hdup[2][2][Hc];
    __shared__ __align__(16) ull part[8][96];
    __shared__ __align__(16) float gates[2][192];
    __shared__ __align__(16) ull biasdup[96];

    const float* xg = g_xg;
    float* yout = (layer == 0) ? g_y0 : (layer == 1 ? g_y1 : g_y2);

    const int tid  = threadIdx.x;
    const int rank = blockIdx.x;
    const int B0   = blockIdx.y * 2;

    const int cp = tid % 96;
    const int kq = tid / 96;
    const int kbase = kq * 64;
    const int c0 = 2 * cp;
    const int s  = c0 >> 6;
    const int jl = c0 & 63;
    const int grow = s * 256 + 64 * rank + jl;

    if (tid < 96) {
        int cc0 = 2 * tid;
        int ss = cc0 >> 6, jj = cc0 & 63;
        int gr = ss * 256 + 64 * rank + jj;
        biasdup[tid] = pack2(b_hh[gr], b_hh[gr + 1]);
    }
    for (int idx = tid; idx < 2 * Hc; idx += SCAN_THREADS) {
        hdup[0][idx >> 8][idx & 255] = 0ULL;
    }

    ull wreg[64];
    {
        const float* w0p = w_hh + (size_t)grow * Hc + kbase;
        const float* w1p = w0p + Hc;
#pragma unroll
        for (int i = 0; i < 64; i++) wreg[i] = pack2(__ldg(w0p + i), __ldg(w1p + i));
    }
    __syncthreads();

    const unsigned hbase_u32[2] = { smem_u32(&hdup[0][0][0]), smem_u32(&hdup[1][0][0]) };

    for (int t = 0; t < Tc; t++) {
        const int p = t & 1;

        float xr = 0.f, xz = 0.f, xn = 0.f;
        if (tid < 128) {
            int b = tid >> 6, j = tid & 63;
            const float* xp = xg + ((size_t)(B0 + b) * Tc + t) * Gc + 64 * rank + j;
            xr = __ldg(xp); xz = __ldg(xp + 256); xn = __ldg(xp + 512);
        }

        {
            const ull* h0 = &hdup[p][0][kbase];
            const ull* h1 = &hdup[p][1][kbase];
            ull a0 = 0ULL, a1 = 0ULL, bb0 = 0ULL, bb1 = 0ULL;
#pragma unroll
            for (int i = 0; i < 64; i += 2) {
                ulonglong2 ha = *(const ulonglong2*)(h0 + i);
                ulonglong2 hb = *(const ulonglong2*)(h1 + i);
                a0  = fma2(ha.x, wreg[i],     a0);
                bb0 = fma2(hb.x, wreg[i],     bb0);
                a1  = fma2(ha.y, wreg[i + 1], a1);
                bb1 = fma2(hb.y, wreg[i + 1], bb1);
            }
            part[kq * 2 + 0][cp] = add2(a0, a1);
            part[kq * 2 + 1][cp] = add2(bb0, bb1);
        }
        __syncthreads();

        if (tid < 192) {
            int b = tid / 96, c = tid % 96;
            ull v = add2(add2(part[0 * 2 + b][c], part[1 * 2 + b][c]),
                         add2(part[2 * 2 + b][c], part[3 * 2 + b][c]));
            v = add2(v, biasdup[c]);
            *(ull*)&gates[b][2 * c] = v;
        }
        __syncthreads();

        if (tid < 128) {
            int b = tid >> 6, j = tid & 63;
            int slot = 64 * rank + j;
            float hr = gates[b][j];
            float hz = gates[b][64 + j];
            float hn = gates[b][128 + j];
            float hp, dummy;
            unpack2(hdup[p][b][slot], hp, dummy);
            float r = sigmoidf_(xr + hr);
            float z = sigmoidf_(xz + hz);
            float n = tanhf(xn + r * hn);
            float hnew = fmaf(z, hp - n, n);
            ull hd = pack2(hnew, hnew);
            hdup[p ^ 1][b][slot] = hd;
            unsigned laddr = hbase_u32[p ^ 1] + (unsigned)((b * Hc + slot) * 8);
#pragma unroll
            for (int pr = 1; pr < 4; pr++) {
                unsigned r2 = (rank + pr) & 3;
                unsigned raddr;
                asm("mapa.shared::cluster.u32 %0, %1, %2;" : "=r"(raddr) : "r"(laddr), "r"(r2));
                asm volatile("st.shared::cluster.b64 [%0], %1;" :: "r"(raddr), "l"(hd) : "memory");
            }
            yout[((size_t)(B0 + b) * Tc + t) * Hc + slot] = hnew;
        }

        cluster_sync_();
    }
}

// ---------------- FC head ----------------
__global__ __launch_bounds__(128) void fc_kernel(const float* __restrict__ fc1_w,
                                                 const float* __restrict__ fc1_b,
                                                 const float* __restrict__ fco_w,
                                                 const float* __restrict__ fco_b,
                                                 float* __restrict__ out) {
    int b = blockIdx.x;
    int f = threadIdx.x;
    const float* last = g_y2 + ((size_t)b * Tc + (Tc - 1)) * Hc;
    __shared__ float ls[256];
    for (int k = f; k < 256; k += 128) ls[k] = last[k];
    __syncthreads();
    float acc = fc1_b[f];
    const float* wr = fc1_w + (size_t)f * 256;
#pragma unroll 8
    for (int k = 0; k < 256; k++) acc = fmaf(ls[k], wr[k], acc);
    float z = fmaxf(acc, 0.0f);
    float v = z * fco_w[f];
#pragma unroll
    for (int o = 16; o > 0; o >>= 1) v += __shfl_xor_sync(0xffffffffu, v, o);
    __shared__ float ws[4];
    if ((f & 31) == 0) ws[f >> 5] = v;
    __syncthreads();
    if (f == 0) out[b] = ws[0] + ws[1] + ws[2] + ws[3] + fco_b[0];
}

// ---------------- launch ----------------
extern "C" void kernel_launch(void* const* d_in, const int* in_sizes, int n_in,
                              void* d_out, int out_size) {
    const float* x     = (const float*)d_in[0];
    const float* w_ih0 = (const float*)d_in[1];
    const float* w_hh0 = (const float*)d_in[2];
    const float* b_ih0 = (const float*)d_in[3];
    const float* b_hh0 = (const float*)d_in[4];
    const float* w_ih1 = (const float*)d_in[5];
    const float* w_hh1 = (const float*)d_in[6];
    const float* b_ih1 = (const float*)d_in[7];
    const float* b_hh1 = (const float*)d_in[8];
    const float* w_ih2 = (const float*)d_in[9];
    const float* w_hh2 = (const float*)d_in[10];
    const float* b_ih2 = (const float*)d_in[11];
    const float* b_hh2 = (const float*)d_in[12];
    const float* fc1_w = (const float*)d_in[13];
    const float* fc1_b = (const float*)d_in[14];
    const float* fco_w = (const float*)d_in[15];
    const float* fco_b = (const float*)d_in[16];
    float* out = (float*)d_out;

    cudaFuncSetAttribute(gemm_tc, cudaFuncAttributeMaxDynamicSharedMemorySize, GEMM_SMEM);

    float* y0p; cudaGetSymbolAddress((void**)&y0p, g_y0);
    float* y1p; cudaGetSymbolAddress((void**)&y1p, g_y1);

    dim3 ggrid(6, 256);      // N tiles x M tiles
    dim3 sgrid(4, 32);       // 32 clusters x 4 CTAs

    // layer 0
    gemm_tc<<<ggrid, 256, GEMM_SMEM>>>(x, w_ih0, b_ih0, Ic);
    scan_kernel<<<sgrid, SCAN_THREADS>>>(w_hh0, b_hh0, 0);
    // layer 1
    gemm_tc<<<ggrid, 256, GEMM_SMEM>>>(y0p, w_ih1, b_ih1, Hc);
    scan_kernel<<<sgrid, SCAN_THREADS>>>(w_hh1, b_hh1, 1);
    // layer 2
    gemm_tc<<<ggrid, 256, GEMM_SMEM>>>(y1p, w_ih2, b_ih2, Hc);
    scan_kernel<<<sgrid, SCAN_THREADS>>>(w_hh2, b_hh2, 2);
    // head
    fc_kernel<<<64, 128>>>(fc1_w, fc1_b, fco_w, fco_b, out);
}

// round 8
// speedup vs baseline: 2.4998x; 1.0742x over previous
#include <cuda_runtime.h>
#include <cuda_bf16.h>
#include <stdint.h>
#include <math.h>

typedef unsigned long long ull;

// Problem constants
#define Bc 64
#define Tc 512
#define Ic 2048
#define Hc 256
#define Gc 768   // 3*H
#define Mr ((size_t)Bc * Tc)   // 32768 rows

// ---------------- device scratch (no allocations allowed) ----------------
__device__ float g_xg[Mr * Gc];     // xg buffer, reused per layer
__device__ float g_y0[Mr * Hc];
__device__ float g_y1[Mr * Hc];
__device__ float g_y2[Mr * Hc];
// pre-converted bf16 split operands (row-major, same layout as fp32 sources)
__device__ __nv_bfloat16 g_Ahi[Mr * Ic];
__device__ __nv_bfloat16 g_Alo[Mr * Ic];
__device__ __nv_bfloat16 g_Whi[(size_t)Gc * Ic];
__device__ __nv_bfloat16 g_Wlo[(size_t)Gc * Ic];

// ---------------- packed f32x2 helpers ----------------
__device__ __forceinline__ ull pack2(float x, float y) {
    ull r; asm("mov.b64 %0, {%1, %2};" : "=l"(r) : "f"(x), "f"(y)); return r;
}
__device__ __forceinline__ void unpack2(ull v, float& x, float& y) {
    asm("mov.b64 {%0, %1}, %2;" : "=f"(x), "=f"(y) : "l"(v));
}
__device__ __forceinline__ ull fma2(ull a, ull b, ull c) {
    ull d; asm("fma.rn.f32x2 %0, %1, %2, %3;" : "=l"(d) : "l"(a), "l"(b), "l"(c)); return d;
}
__device__ __forceinline__ ull add2(ull a, ull b) {
    ull d; asm("add.rn.f32x2 %0, %1, %2;" : "=l"(d) : "l"(a), "l"(b)); return d;
}
__device__ __forceinline__ float sigmoidf_(float x) { return 1.0f / (1.0f + __expf(-x)); }
__device__ __forceinline__ unsigned smem_u32(const void* p) {
    return (unsigned)__cvta_generic_to_shared(p);
}

// ---------------- mma.sync helpers ----------------
__device__ __forceinline__ void ldsm_x4(uint32_t& r0, uint32_t& r1, uint32_t& r2, uint32_t& r3,
                                        uint32_t addr) {
    asm volatile("ldmatrix.sync.aligned.m8n8.x4.shared.b16 {%0,%1,%2,%3}, [%4];"
                 : "=r"(r0), "=r"(r1), "=r"(r2), "=r"(r3) : "r"(addr));
}
__device__ __forceinline__ void mma_bf16(float& d0, float& d1, float& d2, float& d3,
                                         uint32_t a0, uint32_t a1, uint32_t a2, uint32_t a3,
                                         uint32_t b0, uint32_t b1) {
    asm volatile(
        "mma.sync.aligned.m16n8k16.row.col.f32.bf16.bf16.f32 "
        "{%0,%1,%2,%3},{%4,%5,%6,%7},{%8,%9},{%0,%1,%2,%3};"
        : "+f"(d0), "+f"(d1), "+f"(d2), "+f"(d3)
        : "r"(a0), "r"(a1), "r"(a2), "r"(a3), "r"(b0), "r"(b1));
}

// ---------------- convert: fp32 -> bf16 hi/lo (row-major, done ONCE) ----------------
__global__ __launch_bounds__(256) void convert_split(const float* __restrict__ src,
                                                     __nv_bfloat16* __restrict__ hi,
                                                     __nv_bfloat16* __restrict__ lo,
                                                     size_t total8) {
    size_t i = (size_t)blockIdx.x * 256 + threadIdx.x;
    if (i >= total8) return;
    const float4* s = (const float4*)src + i * 2;
    float4 v0 = s[0], v1 = s[1];
    float f[8] = {v0.x, v0.y, v0.z, v0.w, v1.x, v1.y, v1.z, v1.w};
    union { __nv_bfloat16 b[8]; uint4 u; } H, L;
#pragma unroll
    for (int j = 0; j < 8; j++) {
        H.b[j] = __float2bfloat16(f[j]);
        L.b[j] = __float2bfloat16(f[j] - __bfloat162float(H.b[j]));
    }
    ((uint4*)hi)[i] = H.u;
    ((uint4*)lo)[i] = L.u;
}

// ---------------- HMMA GEMM: g_xg[m,n] = A[m,:] . W[n,:] + bias[n] ----------------
// BM=BN=128, BK=32, 256 threads (8 warps, warp tile 32x64).
// Split-bf16 3-term: acc += Ahi*Whi + Ahi*Wlo + Alo*Whi (fp32 accumulate).
// SMEM: per stage 4 tiles of 128 x 32 bf16 (rows padded to 40 elems; 80B = 5*16B aligned,
// 20-bank row stride -> conflict-free ldmatrix).
#define LDAp 40
#define TILE_E (128 * LDAp)                 // elems per tile
#define STAGE_E (4 * TILE_E)                // Ahi, Alo, Whi, Wlo
#define GEMM_SMEM (2 * STAGE_E * 2)         // bytes (2 stages, bf16)

__global__ __launch_bounds__(256, 1)
void gemm_tc(const __nv_bfloat16* __restrict__ Ahi, const __nv_bfloat16* __restrict__ Alo,
             const __nv_bfloat16* __restrict__ Whi, const __nv_bfloat16* __restrict__ Wlo,
             const float* __restrict__ bias, int K) {
    extern __shared__ __nv_bfloat16 sm[];
    const uint32_t sbase = smem_u32(sm);
    const int tid = threadIdx.x, lane = tid & 31, wid = tid >> 5;
    const int wm = wid & 3, wn = wid >> 2;
    const int m0 = blockIdx.y * 128, n0 = blockIdx.x * 128;
    const int nkb = K >> 5;

    // per-thread copy coords: u = i*256+tid; row = u>>2, quad = u&3 (uint4 = 8 bf16)
    const int r0r = tid >> 2, q0 = tid & 3;
    const int r1r = (256 + tid) >> 2, q1 = tid & 3;   // i=1: row = 64 + (tid>>2)

    // GMEM staging: 8 uint4 per chunk (Ahi x2, Alo x2, Whi x2, Wlo x2)
    uint4 rg[8];
    {
        size_t a0 = (size_t)(m0 + r0r) * K + q0 * 8;
        size_t a1 = (size_t)(m0 + r1r) * K + q1 * 8;
        size_t w0 = (size_t)(n0 + r0r) * K + q0 * 8;
        size_t w1 = (size_t)(n0 + r1r) * K + q1 * 8;
        rg[0] = *(const uint4*)(Ahi + a0); rg[1] = *(const uint4*)(Ahi + a1);
        rg[2] = *(const uint4*)(Alo + a0); rg[3] = *(const uint4*)(Alo + a1);
        rg[4] = *(const uint4*)(Whi + w0); rg[5] = *(const uint4*)(Whi + w1);
        rg[6] = *(const uint4*)(Wlo + w0); rg[7] = *(const uint4*)(Wlo + w1);
    }

    const int lrow = lane & 15, lcol = (lane >> 4) * 8;
    const uint32_t offA = ((wm * 32 + lrow) * LDAp + lcol) * 2;
    const uint32_t offB = ((wn * 64 + lrow) * LDAp + lcol) * 2;

    float acc[2][8][4];
#pragma unroll
    for (int i = 0; i < 2; i++)
#pragma unroll
        for (int j = 0; j < 8; j++)
#pragma unroll
            for (int q = 0; q < 4; q++) acc[i][j][q] = 0.0f;

    const int e0 = r0r * LDAp + q0 * 8;
    const int e1 = r1r * LDAp + q1 * 8;

    for (int kb = 0; kb < nkb; kb++) {
        const int p = kb & 1;
        __nv_bfloat16* st = sm + p * STAGE_E;
        *(uint4*)(st + e0)              = rg[0];
        *(uint4*)(st + e1)              = rg[1];
        *(uint4*)(st + TILE_E + e0)     = rg[2];
        *(uint4*)(st + TILE_E + e1)     = rg[3];
        *(uint4*)(st + 2 * TILE_E + e0) = rg[4];
        *(uint4*)(st + 2 * TILE_E + e1) = rg[5];
        *(uint4*)(st + 3 * TILE_E + e0) = rg[6];
        *(uint4*)(st + 3 * TILE_E + e1) = rg[7];
        __syncthreads();
        if (kb + 1 < nkb) {
            int kc = (kb + 1) * 32;
            size_t a0 = (size_t)(m0 + r0r) * K + kc + q0 * 8;
            size_t a1 = (size_t)(m0 + r1r) * K + kc + q1 * 8;
            size_t w0 = (size_t)(n0 + r0r) * K + kc + q0 * 8;
            size_t w1 = (size_t)(n0 + r1r) * K + kc + q1 * 8;
            rg[0] = *(const uint4*)(Ahi + a0); rg[1] = *(const uint4*)(Ahi + a1);
            rg[2] = *(const uint4*)(Alo + a0); rg[3] = *(const uint4*)(Alo + a1);
            rg[4] = *(const uint4*)(Whi + w0); rg[5] = *(const uint4*)(Whi + w1);
            rg[6] = *(const uint4*)(Wlo + w0); rg[7] = *(const uint4*)(Wlo + w1);
        }
        const uint32_t bAhi = sbase + (uint32_t)(p * STAGE_E) * 2 + offA;
        const uint32_t bAlo = bAhi + TILE_E * 2;
        const uint32_t bWhi = sbase + (uint32_t)(p * STAGE_E) * 2 + 2 * TILE_E * 2 + offB;
        const uint32_t bWlo = bWhi + TILE_E * 2;
#pragma unroll
        for (int ks = 0; ks < 2; ks++) {
            const uint32_t ko = ks * 32;  // 16 elems * 2B
            uint32_t ah[2][4], al[2][4];
#pragma unroll
            for (int ma = 0; ma < 2; ma++) {
                ldsm_x4(ah[ma][0], ah[ma][1], ah[ma][2], ah[ma][3],
                        bAhi + ko + ma * 16 * LDAp * 2);
                ldsm_x4(al[ma][0], al[ma][1], al[ma][2], al[ma][3],
                        bAlo + ko + ma * 16 * LDAp * 2);
            }
            uint32_t wh[4][4], wl[4][4];
#pragma unroll
            for (int pa = 0; pa < 4; pa++) {
                ldsm_x4(wh[pa][0], wh[pa][1], wh[pa][2], wh[pa][3],
                        bWhi + ko + pa * 16 * LDAp * 2);
                ldsm_x4(wl[pa][0], wl[pa][1], wl[pa][2], wl[pa][3],
                        bWlo + ko + pa * 16 * LDAp * 2);
            }
#pragma unroll
            for (int ma = 0; ma < 2; ma++) {
#pragma unroll
                for (int na = 0; na < 8; na++) {
                    const int pa = na >> 1, hf = na & 1;
                    float* d = acc[ma][na];
                    mma_bf16(d[0], d[1], d[2], d[3],
                             ah[ma][0], ah[ma][1], ah[ma][2], ah[ma][3],
                             wh[pa][hf], wh[pa][hf + 2]);
                    mma_bf16(d[0], d[1], d[2], d[3],
                             ah[ma][0], ah[ma][1], ah[ma][2], ah[ma][3],
                             wl[pa][hf], wl[pa][hf + 2]);
                    mma_bf16(d[0], d[1], d[2], d[3],
                             al[ma][0], al[ma][1], al[ma][2], al[ma][3],
                             wh[pa][hf], wh[pa][hf + 2]);
                }
            }
        }
        __syncthreads();
    }

    // epilogue
#pragma unroll
    for (int ma = 0; ma < 2; ma++) {
#pragma unroll
        for (int na = 0; na < 8; na++) {
            int row = m0 + wm * 32 + ma * 16 + (lane >> 2);
            int col = n0 + wn * 64 + na * 8 + (lane & 3) * 2;
            float b0 = __ldg(bias + col), b1 = __ldg(bias + col + 1);
            float* d = acc[ma][na];
            *(float2*)&g_xg[(size_t)row * Gc + col] = make_float2(d[0] + b0, d[1] + b1);
            *(float2*)&g_xg[(size_t)(row + 8) * Gc + col] = make_float2(d[2] + b0, d[3] + b1);
        }
    }
}

// ---------------- cluster-based persistent recurrent scan ----------------
#define SCAN_THREADS 384

__device__ __forceinline__ void cluster_sync_() {
    asm volatile("barrier.cluster.arrive.aligned;" ::: "memory");
    asm volatile("barrier.cluster.wait.aligned;" ::: "memory");
}

__global__ __launch_bounds__(SCAN_THREADS, 1) __cluster_dims__(4, 1, 1)
void scan_kernel(const float* __restrict__ w_hh,
                 const float* __restrict__ b_hh,
                 int layer) {
    __shared__ __align__(16) ull hdup[2][2][Hc];   // [buf][batch][k] = (h,h)
    __shared__ __align__(16) ull part[8][96];      // [kq*2+b][cp] packed col-pair partials
    __shared__ __align__(16) float biasf[192];     // b_hh slice (gate-major)

    const float* xg = g_xg;
    float* yout = (layer == 0) ? g_y0 : (layer == 1 ? g_y1 : g_y2);

    const int tid  = threadIdx.x;
    const int rank = blockIdx.x;
    const int B0   = blockIdx.y * 2;

    const int cp = tid % 96;
    const int kq = tid / 96;
    const int kbase = kq * 64;
    const int c0 = 2 * cp;
    const int s  = c0 >> 6;
    const int jl = c0 & 63;
    const int grow = s * 256 + 64 * rank + jl;

    if (tid < 192) {
        int ss = tid >> 6, jj = tid & 63;
        biasf[tid] = b_hh[ss * 256 + 64 * rank + jj];
    }
    for (int idx = tid; idx < 2 * Hc; idx += SCAN_THREADS) {
        hdup[0][idx >> 8][idx & 255] = 0ULL;
    }

    ull wreg[64];
    {
        const float* w0p = w_hh + (size_t)grow * Hc + kbase;
        const float* w1p = w0p + Hc;
#pragma unroll
        for (int i = 0; i < 64; i++) wreg[i] = pack2(__ldg(w0p + i), __ldg(w1p + i));
    }
    __syncthreads();

    const unsigned hbase_u32[2] = { smem_u32(&hdup[0][0][0]), smem_u32(&hdup[1][0][0]) };
    const float* partf = (const float*)part;

    for (int t = 0; t < Tc; t++) {
        const int p = t & 1;

        float xr = 0.f, xz = 0.f, xn = 0.f;
        if (tid < 128) {
            int b = tid >> 6, j = tid & 63;
            const float* xp = xg + ((size_t)(B0 + b) * Tc + t) * Gc + 64 * rank + j;
            xr = __ldg(xp); xz = __ldg(xp + 256); xn = __ldg(xp + 512);
        }

        {
            const ull* h0 = &hdup[p][0][kbase];
            const ull* h1 = &hdup[p][1][kbase];
            ull a0 = 0ULL, a1 = 0ULL, bb0 = 0ULL, bb1 = 0ULL;
#pragma unroll
            for (int i = 0; i < 64; i += 2) {
                ulonglong2 ha = *(const ulonglong2*)(h0 + i);
                ulonglong2 hb = *(const ulonglong2*)(h1 + i);
                a0  = fma2(ha.x, wreg[i],     a0);
                bb0 = fma2(hb.x, wreg[i],     bb0);
                a1  = fma2(ha.y, wreg[i + 1], a1);
                bb1 = fma2(hb.y, wreg[i + 1], bb1);
            }
            part[kq * 2 + 0][cp] = add2(a0, a1);
            part[kq * 2 + 1][cp] = add2(bb0, bb1);
        }
        __syncthreads();

        // merged reduce + pointwise: thread (b, j) sums 4 k-quarter partials per gate
        if (tid < 128) {
            int b = tid >> 6, j = tid & 63;
            int slot = 64 * rank + j;
            int cpr = (j >> 1), par = j & 1;
            // gate columns: r -> cpr, z -> 32+cpr, n -> 64+cpr
            float hr = 0.f, hz = 0.f, hn = 0.f;
#pragma unroll
            for (int k = 0; k < 4; k++) {
                int base = ((k * 2 + b) * 96) * 2;
                hr += partf[base + (cpr) * 2 + par];
                hz += partf[base + (32 + cpr) * 2 + par];
                hn += partf[base + (64 + cpr) * 2 + par];
            }
            hr += biasf[j]; hz += biasf[64 + j]; hn += biasf[128 + j];
            float hp, dummy;
            unpack2(hdup[p][b][slot], hp, dummy);
            float r = sigmoidf_(xr + hr);
            float z = sigmoidf_(xz + hz);
            float n = tanhf(xn + r * hn);
            float hnew = fmaf(z, hp - n, n);
            ull hd = pack2(hnew, hnew);
            hdup[p ^ 1][b][slot] = hd;
            unsigned laddr = hbase_u32[p ^ 1] + (unsigned)((b * Hc + slot) * 8);
#pragma unroll
            for (int pr = 1; pr < 4; pr++) {
                unsigned r2 = (rank + pr) & 3;
                unsigned raddr;
                asm("mapa.shared::cluster.u32 %0, %1, %2;" : "=r"(raddr) : "r"(laddr), "r"(r2));
                asm volatile("st.shared::cluster.b64 [%0], %1;" :: "r"(raddr), "l"(hd) : "memory");
            }
            if (layer != 2 || t == Tc - 1)
                yout[((size_t)(B0 + b) * Tc + t) * Hc + slot] = hnew;
        }

        cluster_sync_();
    }
}

// ---------------- FC head ----------------
__global__ __launch_bounds__(128) void fc_kernel(const float* __restrict__ fc1_w,
                                                 const float* __restrict__ fc1_b,
                                                 const float* __restrict__ fco_w,
                                                 const float* __restrict__ fco_b,
                                                 float* __restrict__ out) {
    int b = blockIdx.x;
    int f = threadIdx.x;
    const float* last = g_y2 + ((size_t)b * Tc + (Tc - 1)) * Hc;
    __shared__ float ls[256];
    for (int k = f; k < 256; k += 128) ls[k] = last[k];
    __syncthreads();
    float acc = fc1_b[f];
    const float* wr = fc1_w + (size_t)f * 256;
#pragma unroll 8
    for (int k = 0; k < 256; k++) acc = fmaf(ls[k], wr[k], acc);
    float z = fmaxf(acc, 0.0f);
    float v = z * fco_w[f];
#pragma unroll
    for (int o = 16; o > 0; o >>= 1) v += __shfl_xor_sync(0xffffffffu, v, o);
    __shared__ float ws[4];
    if ((f & 31) == 0) ws[f >> 5] = v;
    __syncthreads();
    if (f == 0) out[b] = ws[0] + ws[1] + ws[2] + ws[3] + fco_b[0];
}

// ---------------- launch ----------------
extern "C" void kernel_launch(void* const* d_in, const int* in_sizes, int n_in,
                              void* d_out, int out_size) {
    const float* x     = (const float*)d_in[0];
    const float* w_ih0 = (const float*)d_in[1];
    const float* w_hh0 = (const float*)d_in[2];
    const float* b_ih0 = (const float*)d_in[3];
    const float* b_hh0 = (const float*)d_in[4];
    const float* w_ih1 = (const float*)d_in[5];
    const float* w_hh1 = (const float*)d_in[6];
    const float* b_ih1 = (const float*)d_in[7];
    const float* b_hh1 = (const float*)d_in[8];
    const float* w_ih2 = (const float*)d_in[9];
    const float* w_hh2 = (const float*)d_in[10];
    const float* b_ih2 = (const float*)d_in[11];
    const float* b_hh2 = (const float*)d_in[12];
    const float* fc1_w = (const float*)d_in[13];
    const float* fc1_b = (const float*)d_in[14];
    const float* fco_w = (const float*)d_in[15];
    const float* fco_b = (const float*)d_in[16];
    float* out = (float*)d_out;

    cudaFuncSetAttribute(gemm_tc, cudaFuncAttributeMaxDynamicSharedMemorySize, GEMM_SMEM);

    __nv_bfloat16 *Ahi, *Alo, *Whi, *Wlo;
    cudaGetSymbolAddress((void**)&Ahi, g_Ahi);
    cudaGetSymbolAddress((void**)&Alo, g_Alo);
    cudaGetSymbolAddress((void**)&Whi, g_Whi);
    cudaGetSymbolAddress((void**)&Wlo, g_Wlo);
    float* y0p; cudaGetSymbolAddress((void**)&y0p, g_y0);
    float* y1p; cudaGetSymbolAddress((void**)&y1p, g_y1);

    dim3 ggrid(6, 256);      // N tiles x M tiles
    dim3 sgrid(4, 32);       // 32 clusters x 4 CTAs

    const size_t a8big = Mr * Ic / 8, w8big = (size_t)Gc * Ic / 8;
    const size_t a8sm  = Mr * Hc / 8, w8sm  = (size_t)Gc * Hc / 8;

    // layer 0
    convert_split<<<(unsigned)((a8big + 255) / 256), 256>>>(x, Ahi, Alo, a8big);
    convert_split<<<(unsigned)((w8big + 255) / 256), 256>>>(w_ih0, Whi, Wlo, w8big);
    gemm_tc<<<ggrid, 256, GEMM_SMEM>>>(Ahi, Alo, Whi, Wlo, b_ih0, Ic);
    scan_kernel<<<sgrid, SCAN_THREADS>>>(w_hh0, b_hh0, 0);
    // layer 1
    convert_split<<<(unsigned)((a8sm + 255) / 256), 256>>>(y0p, Ahi, Alo, a8sm);
    convert_split<<<(unsigned)((w8sm + 255) / 256), 256>>>(w_ih1, Whi, Wlo, w8sm);
    gemm_tc<<<ggrid, 256, GEMM_SMEM>>>(Ahi, Alo, Whi, Wlo, b_ih1, Hc);
    scan_kernel<<<sgrid, SCAN_THREADS>>>(w_hh1, b_hh1, 1);
    // layer 2
    convert_split<<<(unsigned)((a8sm + 255) / 256), 256>>>(y1p, Ahi, Alo, a8sm);
    convert_split<<<(unsigned)((w8sm + 255) / 256), 256>>>(w_ih2, Whi, Wlo, w8sm);
    gemm_tc<<<ggrid, 256, GEMM_SMEM>>>(Ahi, Alo, Whi, Wlo, b_ih2, Hc);
    scan_kernel<<<sgrid, SCAN_THREADS>>>(w_hh2, b_hh2, 2);
    // head
    fc_kernel<<<64, 128>>>(fc1_w, fc1_b, fco_w, fco_b, out);
}

// round 11
// speedup vs baseline: 2.9688x; 1.1876x over previous
#include <cuda_runtime.h>
#include <cuda_bf16.h>
#include <stdint.h>
#include <math.h>

typedef unsigned long long ull;

// Problem constants
#define Bc 64
#define Tc 512
#define Ic 2048
#define Hc 256
#define Gc 768   // 3*H
#define Mr ((size_t)Bc * Tc)   // 32768 rows

// ---------------- device scratch (no allocations allowed) ----------------
__device__ float g_xg[Mr * Gc];     // xg buffer, reused per layer
__device__ float g_y0[Mr * Hc];
__device__ float g_y1[Mr * Hc];
__device__ float g_y2[Mr * Hc];
// pre-converted bf16 split operands (row-major, same layout as fp32 sources)
__device__ __nv_bfloat16 g_Ahi[Mr * Ic];
__device__ __nv_bfloat16 g_Alo[Mr * Ic];
__device__ __nv_bfloat16 g_Whi[(size_t)Gc * Ic];
__device__ __nv_bfloat16 g_Wlo[(size_t)Gc * Ic];

// ---------------- packed f32x2 helpers ----------------
__device__ __forceinline__ ull pack2(float x, float y) {
    ull r; asm("mov.b64 %0, {%1, %2};" : "=l"(r) : "f"(x), "f"(y)); return r;
}
__device__ __forceinline__ void unpack2(ull v, float& x, float& y) {
    asm("mov.b64 {%0, %1}, %2;" : "=f"(x), "=f"(y) : "l"(v));
}
__device__ __forceinline__ ull fma2(ull a, ull b, ull c) {
    ull d; asm("fma.rn.f32x2 %0, %1, %2, %3;" : "=l"(d) : "l"(a), "l"(b), "l"(c)); return d;
}
__device__ __forceinline__ ull add2(ull a, ull b) {
    ull d; asm("add.rn.f32x2 %0, %1, %2;" : "=l"(d) : "l"(a), "l"(b)); return d;
}
__device__ __forceinline__ float sigmoidf_(float x) {
    return __fdividef(1.0f, 1.0f + __expf(-x));
}
__device__ __forceinline__ float tanhf_(float x) {
    float a = fabsf(x);
    float e = __expf(-2.0f * a);
    float r = __fdividef(1.0f - e, 1.0f + e);
    return copysignf(r, x);
}
__device__ __forceinline__ unsigned smem_u32(const void* p) {
    return (unsigned)__cvta_generic_to_shared(p);
}

// ---------------- mma.sync / cp.async helpers ----------------
__device__ __forceinline__ void ldsm_x4(uint32_t& r0, uint32_t& r1, uint32_t& r2, uint32_t& r3,
                                        uint32_t addr) {
    asm volatile("ldmatrix.sync.aligned.m8n8.x4.shared.b16 {%0,%1,%2,%3}, [%4];"
                 : "=r"(r0), "=r"(r1), "=r"(r2), "=r"(r3) : "r"(addr));
}
__device__ __forceinline__ void mma_bf16(float& d0, float& d1, float& d2, float& d3,
                                         uint32_t a0, uint32_t a1, uint32_t a2, uint32_t a3,
                                         uint32_t b0, uint32_t b1) {
    asm volatile(
        "mma.sync.aligned.m16n8k16.row.col.f32.bf16.bf16.f32 "
        "{%0,%1,%2,%3},{%4,%5,%6,%7},{%8,%9},{%0,%1,%2,%3};"
        : "+f"(d0), "+f"(d1), "+f"(d2), "+f"(d3)
        : "r"(a0), "r"(a1), "r"(a2), "r"(a3), "r"(b0), "r"(b1));
}
__device__ __forceinline__ void cp16(uint32_t dst, const void* src) {
    asm volatile("cp.async.cg.shared.global [%0], [%1], 16;" :: "r"(dst), "l"(src));
}

// ---------------- convert: fp32 -> bf16 hi/lo (row-major, done ONCE) ----------------
__global__ __launch_bounds__(256) void convert_split(const float* __restrict__ src,
                                                     __nv_bfloat16* __restrict__ hi,
                                                     __nv_bfloat16* __restrict__ lo,
                                                     size_t total8) {
    size_t i = (size_t)blockIdx.x * 256 + threadIdx.x;
    if (i >= total8) return;
    const float4* s = (const float4*)src + i * 2;
    float4 v0 = s[0], v1 = s[1];
    float f[8] = {v0.x, v0.y, v0.z, v0.w, v1.x, v1.y, v1.z, v1.w};
    union { __nv_bfloat16 b[8]; uint4 u; } H, L;
#pragma unroll
    for (int j = 0; j < 8; j++) {
        H.b[j] = __float2bfloat16(f[j]);
        L.b[j] = __float2bfloat16(f[j] - __bfloat162float(H.b[j]));
    }
    ((uint4*)hi)[i] = H.u;
    ((uint4*)lo)[i] = L.u;
}

// ---------------- HMMA GEMM: g_xg[m,n] = A[m,:] . W[n,:] + bias[n] ----------------
// BM=BN=128, BK=32, 256 threads (8 warps, warp tile 32x64), 2 CTAs/SM.
// Split-bf16 3-term: acc += Ahi*Whi + Ahi*Wlo + Alo*Whi (fp32 accumulate).
// cp.async 2-stage pipeline; SMEM rows padded to 40 elems (80B, conflict-free ldmatrix).
#define LDAp 40
#define TILE_E (128 * LDAp)                 // elems per tile
#define STAGE_E (4 * TILE_E)                // Ahi, Alo, Whi, Wlo
#define GEMM_SMEM (2 * STAGE_E * 2)         // bytes (2 stages, bf16) = 80 KB

__global__ __launch_bounds__(256, 2)
void gemm_tc(const __nv_bfloat16* __restrict__ Ahi, const __nv_bfloat16* __restrict__ Alo,
             const __nv_bfloat16* __restrict__ Whi, const __nv_bfloat16* __restrict__ Wlo,
             const float* __restrict__ bias, int K) {
    extern __shared__ __nv_bfloat16 sm[];
    const uint32_t sbase = smem_u32(sm);
    const int tid = threadIdx.x, lane = tid & 31, wid = tid >> 5;
    const int wm = wid & 3, wn = wid >> 2;
    const int m0 = blockIdx.y * 128, n0 = blockIdx.x * 128;
    const int nkb = K >> 5;

    // per-thread copy coords: rows r0/r1, 16B quad q
    const int r0 = tid >> 2, r1 = 64 + r0, q = tid & 3;
    const uint32_t e0 = (uint32_t)(r0 * LDAp + q * 8) * 2;   // byte offsets in tile
    const uint32_t e1 = (uint32_t)(r1 * LDAp + q * 8) * 2;

    const __nv_bfloat16* a0p = Ahi + (size_t)(m0 + r0) * K + q * 8;
    const __nv_bfloat16* a1p = Ahi + (size_t)(m0 + r1) * K + q * 8;
    const __nv_bfloat16* l0p = Alo + (size_t)(m0 + r0) * K + q * 8;
    const __nv_bfloat16* l1p = Alo + (size_t)(m0 + r1) * K + q * 8;
    const __nv_bfloat16* w0p = Whi + (size_t)(n0 + r0) * K + q * 8;
    const __nv_bfloat16* w1p = Whi + (size_t)(n0 + r1) * K + q * 8;
    const __nv_bfloat16* v0p = Wlo + (size_t)(n0 + r0) * K + q * 8;
    const __nv_bfloat16* v1p = Wlo + (size_t)(n0 + r1) * K + q * 8;

    const int lrow = lane & 15, lcol = (lane >> 4) * 8;
    const uint32_t offA = ((wm * 32 + lrow) * LDAp + lcol) * 2;
    const uint32_t offB = ((wn * 64 + lrow) * LDAp + lcol) * 2;

    float acc[2][8][4];
#pragma unroll
    for (int i = 0; i < 2; i++)
#pragma unroll
        for (int j = 0; j < 8; j++)
#pragma unroll
            for (int qq = 0; qq < 4; qq++) acc[i][j][qq] = 0.0f;

    // issue stage copies for chunk kb
    auto issue = [&](int kb) {
        const uint32_t st = sbase + (uint32_t)(kb & 1) * STAGE_E * 2;
        const int kc = kb * 32;
        cp16(st + e0, a0p + kc);
        cp16(st + e1, a1p + kc);
        cp16(st + TILE_E * 2 + e0, l0p + kc);
        cp16(st + TILE_E * 2 + e1, l1p + kc);
        cp16(st + 2 * TILE_E * 2 + e0, w0p + kc);
        cp16(st + 2 * TILE_E * 2 + e1, w1p + kc);
        cp16(st + 3 * TILE_E * 2 + e0, v0p + kc);
        cp16(st + 3 * TILE_E * 2 + e1, v1p + kc);
        asm volatile("cp.async.commit_group;");
    };

    issue(0);

    for (int kb = 0; kb < nkb; kb++) {
        if (kb + 1 < nkb) {
            issue(kb + 1);
            asm volatile("cp.async.wait_group 1;");
        } else {
            asm volatile("cp.async.wait_group 0;");
        }
        __syncthreads();

        const int p = kb & 1;
        const uint32_t bAhi = sbase + (uint32_t)p * STAGE_E * 2 + offA;
        const uint32_t bAlo = bAhi + TILE_E * 2;
        const uint32_t bWhi = sbase + (uint32_t)p * STAGE_E * 2 + 2 * TILE_E * 2 + offB;
        const uint32_t bWlo = bWhi + TILE_E * 2;
#pragma unroll
        for (int ks = 0; ks < 2; ks++) {
            const uint32_t ko = ks * 32;  // 16 elems * 2B
            uint32_t ah[2][4], al[2][4];
#pragma unroll
            for (int ma = 0; ma < 2; ma++) {
                ldsm_x4(ah[ma][0], ah[ma][1], ah[ma][2], ah[ma][3],
                        bAhi + ko + ma * 16 * LDAp * 2);
                ldsm_x4(al[ma][0], al[ma][1], al[ma][2], al[ma][3],
                        bAlo + ko + ma * 16 * LDAp * 2);
            }
            uint32_t wh[4][4], wl[4][4];
#pragma unroll
            for (int pa = 0; pa < 4; pa++) {
                ldsm_x4(wh[pa][0], wh[pa][1], wh[pa][2], wh[pa][3],
                        bWhi + ko + pa * 16 * LDAp * 2);
                ldsm_x4(wl[pa][0], wl[pa][1], wl[pa][2], wl[pa][3],
                        bWlo + ko + pa * 16 * LDAp * 2);
            }
#pragma unroll
            for (int ma = 0; ma < 2; ma++) {
#pragma unroll
                for (int na = 0; na < 8; na++) {
                    const int pa = na >> 1, hf = na & 1;
                    float* d = acc[ma][na];
                    mma_bf16(d[0], d[1], d[2], d[3],
                             ah[ma][0], ah[ma][1], ah[ma][2], ah[ma][3],
                             wh[pa][hf], wh[pa][hf + 2]);
                    mma_bf16(d[0], d[1], d[2], d[3],
                             ah[ma][0], ah[ma][1], ah[ma][2], ah[ma][3],
                             wl[pa][hf], wl[pa][hf + 2]);
                    mma_bf16(d[0], d[1], d[2], d[3],
                             al[ma][0], al[ma][1], al[ma][2], al[ma][3],
                             wh[pa][hf], wh[pa][hf + 2]);
                }
            }
        }
        __syncthreads();
    }

    // epilogue
#pragma unroll
    for (int ma = 0; ma < 2; ma++) {
#pragma unroll
        for (int na = 0; na < 8; na++) {
            int row = m0 + wm * 32 + ma * 16 + (lane >> 2);
            int col = n0 + wn * 64 + na * 8 + (lane & 3) * 2;
            float b0 = __ldg(bias + col), b1 = __ldg(bias + col + 1);
            float* d = acc[ma][na];
            *(float2*)&g_xg[(size_t)row * Gc + col] = make_float2(d[0] + b0, d[1] + b1);
            *(float2*)&g_xg[(size_t)(row + 8) * Gc + col] = make_float2(d[2] + b0, d[3] + b1);
        }
    }
}

// ---------------- cluster-based persistent recurrent scan ----------------
#define SCAN_THREADS 384

__device__ __forceinline__ void cluster_sync_() {
    asm volatile("barrier.cluster.arrive.aligned;" ::: "memory");
    asm volatile("barrier.cluster.wait.aligned;" ::: "memory");
}

__global__ __launch_bounds__(SCAN_THREADS, 1) __cluster_dims__(4, 1, 1)
void scan_kernel(const float* __restrict__ w_hh,
                 const float* __restrict__ b_hh,
                 int layer) {
    __shared__ __align__(16) ull hdup[2][2][Hc];   // [buf][batch][k] = (h,h)
    __shared__ __align__(16) ull part[8][96];      // [kq*2+b][cp] packed col-pair partials
    __shared__ __align__(16) float biasf[192];     // b_hh slice (gate-major)

    const float* xg = g_xg;
    float* yout = (layer == 0) ? g_y0 : (layer == 1 ? g_y1 : g_y2);

    const int tid  = threadIdx.x;
    const int rank = blockIdx.x;
    const int B0   = blockIdx.y * 2;

    const int cp = tid % 96;
    const int kq = tid / 96;
    const int kbase = kq * 64;
    const int c0 = 2 * cp;
    const int s  = c0 >> 6;
    const int jl = c0 & 63;
    const int grow = s * 256 + 64 * rank + jl;

    if (tid < 192) {
        int ss = tid >> 6, jj = tid & 63;
        biasf[tid] = b_hh[ss * 256 + 64 * rank + jj];
    }
    for (int idx = tid; idx < 2 * Hc; idx += SCAN_THREADS) {
        hdup[0][idx >> 8][idx & 255] = 0ULL;
    }

    ull wreg[64];
    {
        const float* w0p = w_hh + (size_t)grow * Hc + kbase;
        const float* w1p = w0p + Hc;
#pragma unroll
        for (int i = 0; i < 64; i++) wreg[i] = pack2(__ldg(w0p + i), __ldg(w1p + i));
    }
    __syncthreads();

    const unsigned hbase_u32[2] = { smem_u32(&hdup[0][0][0]), smem_u32(&hdup[1][0][0]) };
    const float* partf = (const float*)part;

    // software-pipelined xg for step 0
    const int pb = (tid < 128) ? (tid >> 6) : 0;
    const int pj = tid & 63;
    const float* xbase = xg + ((size_t)(B0 + pb) * Tc) * Gc + 64 * rank + pj;
    float xr = 0.f, xz = 0.f, xn = 0.f;
    if (tid < 128) {
        const float* xp = xbase;  // t = 0
        xr = __ldg(xp); xz = __ldg(xp + 256); xn = __ldg(xp + 512);
    }

    for (int t = 0; t < Tc; t++) {
        const int p = t & 1;

        {
            const ull* h0 = &hdup[p][0][kbase];
            const ull* h1 = &hdup[p][1][kbase];
            ull a0 = 0ULL, a1 = 0ULL, bb0 = 0ULL, bb1 = 0ULL;
#pragma unroll
            for (int i = 0; i < 64; i += 2) {
                ulonglong2 ha = *(const ulonglong2*)(h0 + i);
                ulonglong2 hb = *(const ulonglong2*)(h1 + i);
                a0  = fma2(ha.x, wreg[i],     a0);
                bb0 = fma2(hb.x, wreg[i],     bb0);
                a1  = fma2(ha.y, wreg[i + 1], a1);
                bb1 = fma2(hb.y, wreg[i + 1], bb1);
            }
            part[kq * 2 + 0][cp] = add2(a0, a1);
            part[kq * 2 + 1][cp] = add2(bb0, bb1);
        }
        __syncthreads();

        // prefetch xg(t+1) early — consumed next iteration
        float nxr = 0.f, nxz = 0.f, nxn = 0.f;
        if (tid < 128 && t + 1 < Tc) {
            const float* xp = xbase + (size_t)(t + 1) * Gc;
            nxr = __ldg(xp); nxz = __ldg(xp + 256); nxn = __ldg(xp + 512);
        }

        // merged reduce + pointwise: thread (b, j) sums 4 k-quarter partials per gate
        if (tid < 128) {
            int b = tid >> 6, j = tid & 63;
            int slot = 64 * rank + j;
            int cpr = (j >> 1), par = j & 1;
            float hr = 0.f, hz = 0.f, hn = 0.f;
#pragma unroll
            for (int k = 0; k < 4; k++) {
                int base = ((k * 2 + b) * 96) * 2;
                hr += partf[base + (cpr) * 2 + par];
                hz += partf[base + (32 + cpr) * 2 + par];
                hn += partf[base + (64 + cpr) * 2 + par];
            }
            hr += biasf[j]; hz += biasf[64 + j]; hn += biasf[128 + j];
            float hp, dummy;
            unpack2(hdup[p][b][slot], hp, dummy);
            float r = sigmoidf_(xr + hr);
            float z = sigmoidf_(xz + hz);
            float n = tanhf_(xn + r * hn);
            float hnew = fmaf(z, hp - n, n);
            ull hd = pack2(hnew, hnew);
            hdup[p ^ 1][b][slot] = hd;
            unsigned laddr = hbase_u32[p ^ 1] + (unsigned)((b * Hc + slot) * 8);
#pragma unroll
            for (int pr = 1; pr < 4; pr++) {
                unsigned r2 = (rank + pr) & 3;
                unsigned raddr;
                asm("mapa.shared::cluster.u32 %0, %1, %2;" : "=r"(raddr) : "r"(laddr), "r"(r2));
                asm volatile("st.shared::cluster.b64 [%0], %1;" :: "r"(raddr), "l"(hd) : "memory");
            }
            if (layer != 2 || t == Tc - 1)
                yout[((size_t)(B0 + b) * Tc + t) * Hc + slot] = hnew;
        }

        cluster_sync_();
        xr = nxr; xz = nxz; xn = nxn;
    }
}

// ---------------- FC head ----------------
__global__ __launch_bounds__(128) void fc_kernel(const float* __restrict__ fc1_w,
                                                 const float* __restrict__ fc1_b,
                                                 const float* __restrict__ fco_w,
                                                 const float* __restrict__ fco_b,
                                                 float* __restrict__ out) {
    int b = blockIdx.x;
    int f = threadIdx.x;
    const float* last = g_y2 + ((size_t)b * Tc + (Tc - 1)) * Hc;
    __shared__ float ls[256];
    for (int k = f; k < 256; k += 128) ls[k] = last[k];
    __syncthreads();
    float acc = fc1_b[f];
    const float* wr = fc1_w + (size_t)f * 256;
#pragma unroll 8
    for (int k = 0; k < 256; k++) acc = fmaf(ls[k], wr[k], acc);
    float z = fmaxf(acc, 0.0f);
    float v = z * fco_w[f];
#pragma unroll
    for (int o = 16; o > 0; o >>= 1) v += __shfl_xor_sync(0xffffffffu, v, o);
    __shared__ float ws[4];
    if ((f & 31) == 0) ws[f >> 5] = v;
    __syncthreads();
    if (f == 0) out[b] = ws[0] + ws[1] + ws[2] + ws[3] + fco_b[0];
}

// ---------------- launch ----------------
extern "C" void kernel_launch(void* const* d_in, const int* in_sizes, int n_in,
                              void* d_out, int out_size) {
    const float* x     = (const float*)d_in[0];
    const float* w_ih0 = (const float*)d_in[1];
    const float* w_hh0 = (const float*)d_in[2];
    const float* b_ih0 = (const float*)d_in[3];
    const float* b_hh0 = (const float*)d_in[4];
    const float* w_ih1 = (const float*)d_in[5];
    const float* w_hh1 = (const float*)d_in[6];
    const float* b_ih1 = (const float*)d_in[7];
    const float* b_hh1 = (const float*)d_in[8];
    const float* w_ih2 = (const float*)d_in[9];
    const float* w_hh2 = (const float*)d_in[10];
    const float* b_ih2 = (const float*)d_in[11];
    const float* b_hh2 = (const float*)d_in[12];
    const float* fc1_w = (const float*)d_in[13];
    const float* fc1_b = (const float*)d_in[14];
    const float* fco_w = (const float*)d_in[15];
    const float* fco_b = (const float*)d_in[16];
    float* out = (float*)d_out;

    cudaFuncSetAttribute(gemm_tc, cudaFuncAttributeMaxDynamicSharedMemorySize, GEMM_SMEM);

    __nv_bfloat16 *Ahi, *Alo, *Whi, *Wlo;
    cudaGetSymbolAddress((void**)&Ahi, g_Ahi);
    cudaGetSymbolAddress((void**)&Alo, g_Alo);
    cudaGetSymbolAddress((void**)&Whi, g_Whi);
    cudaGetSymbolAddress((void**)&Wlo, g_Wlo);
    float* y0p; cudaGetSymbolAddress((void**)&y0p, g_y0);
    float* y1p; cudaGetSymbolAddress((void**)&y1p, g_y1);

    dim3 ggrid(6, 256);      // N tiles x M tiles
    dim3 sgrid(4, 32);       // 32 clusters x 4 CTAs

    const size_t a8big = Mr * Ic / 8, w8big = (size_t)Gc * Ic / 8;
    const size_t a8sm  = Mr * Hc / 8, w8sm  = (size_t)Gc * Hc / 8;

    // layer 0
    convert_split<<<(unsigned)((a8big + 255) / 256), 256>>>(x, Ahi, Alo, a8big);
    convert_split<<<(unsigned)((w8big + 255) / 256), 256>>>(w_ih0, Whi, Wlo, w8big);
    gemm_tc<<<ggrid, 256, GEMM_SMEM>>>(Ahi, Alo, Whi, Wlo, b_ih0, Ic);
    scan_kernel<<<sgrid, SCAN_THREADS>>>(w_hh0, b_hh0, 0);
    // layer 1
    convert_split<<<(unsigned)((a8sm + 255) / 256), 256>>>(y0p, Ahi, Alo, a8sm);
    convert_split<<<(unsigned)((w8sm + 255) / 256), 256>>>(w_ih1, Whi, Wlo, w8sm);
    gemm_tc<<<ggrid, 256, GEMM_SMEM>>>(Ahi, Alo, Whi, Wlo, b_ih1, Hc);
    scan_kernel<<<sgrid, SCAN_THREADS>>>(w_hh1, b_hh1, 1);
    // layer 2
    convert_split<<<(unsigned)((a8sm + 255) / 256), 256>>>(y1p, Ahi, Alo, a8sm);
    convert_split<<<(unsigned)((w8sm + 255) / 256), 256>>>(w_ih2, Whi, Wlo, w8sm);
    gemm_tc<<<ggrid, 256, GEMM_SMEM>>>(Ahi, Alo, Whi, Wlo, b_ih2, Hc);
    scan_kernel<<<sgrid, SCAN_THREADS>>>(w_hh2, b_hh2, 2);
    // head
    fc_kernel<<<64, 128>>>(fc1_w, fc1_b, fco_w, fco_b, out);
}